// round 7
// baseline (speedup 1.0000x reference)
#include <cuda_runtime.h>
#include <math.h>
#include <cstdint>

// Shapes: x[32,512,2048] f32, w_qkv[6144,2048], w_out[2048,2048], out[32,512,2048]

// Scratch (device globals: allocation-free per harness rules)
__device__ float g_q[32L * 16 * 512 * 128];   // [B,H,T,D] fp32 pre-rope
__device__ float g_k[32L * 16 * 512 * 128];
__device__ float g_v[32L * 16 * 512 * 128];   // tf32-rounded at gemm epilogue
__device__ float g_y[32L * 512 * 2048];       // [B,T,C] attn out (tf32-rounded)
__device__ float g_xr[32L * 512 * 2048];      // tf32-rounded x
__device__ float g_wqr[6144L * 2048];         // tf32-rounded w_qkv
__device__ float g_wor[2048L * 2048];         // tf32-rounded w_out
__device__ float g_cos[512 * 32];
__device__ float g_sin[512 * 32];

// ===========================================================================
// Helpers
// ===========================================================================
__device__ __forceinline__ uint32_t smem_u32(const void* p) {
    uint32_t a;
    asm("{ .reg .u64 t; cvta.to.shared.u64 t, %1; cvt.u32.u64 %0, t; }" : "=r"(a) : "l"(p));
    return a;
}
__device__ __forceinline__ uint32_t swz(uint32_t off) { return off ^ ((off >> 3) & 0x70); }

#define CP_ASYNC16(dst, src) \
    asm volatile("cp.async.cg.shared.global [%0], [%1], 16;" :: "r"(dst), "l"(src))
#define CP_COMMIT() asm volatile("cp.async.commit_group;" ::: "memory")
#define CP_WAIT1() asm volatile("cp.async.wait_group 1;" ::: "memory")
#define CP_WAIT0() asm volatile("cp.async.wait_group 0;" ::: "memory")

__device__ __forceinline__ float rnaf(float x) {
    uint32_t r;
    asm("cvt.rna.tf32.f32 %0, %1;" : "=r"(r) : "f"(x));
    return __uint_as_float(r);
}
__device__ __forceinline__ uint32_t U(float x) { return __float_as_uint(x); }

#define MMA_TF32(c, A0, A1, A2, A3, B0, B1) \
    asm volatile("mma.sync.aligned.m16n8k8.row.col.f32.tf32.tf32.f32 " \
        "{%0,%1,%2,%3},{%4,%5,%6,%7},{%8,%9},{%0,%1,%2,%3};" \
        : "+f"((c)[0]), "+f"((c)[1]), "+f"((c)[2]), "+f"((c)[3]) \
        : "r"(A0), "r"(A1), "r"(A2), "r"(A3), "r"(B0), "r"(B1))

#define LDMX4(r, addr) \
    asm volatile("ldmatrix.sync.aligned.m8n8.x4.shared.b16 {%0,%1,%2,%3}, [%4];" \
        : "=r"((r)[0]), "=r"((r)[1]), "=r"((r)[2]), "=r"((r)[3]) : "r"(addr))

// ===========================================================================
// elementwise tf32-round (RNA)
// ===========================================================================
__global__ void round_tf32(const float* __restrict__ in, float* __restrict__ out, int n4)
{
    int i = blockIdx.x * blockDim.x + threadIdx.x;
    if (i >= n4) return;
    float4 v = ((const float4*)in)[i];
    v.x = rnaf(v.x); v.y = rnaf(v.y); v.z = rnaf(v.z); v.w = rnaf(v.w);
    ((float4*)out)[i] = v;
}

// rope tables (double-precision build, matches numpy float64 path)
__global__ void build_tables()
{
    int i = blockIdx.x * blockDim.x + threadIdx.x;
    if (i >= 512 * 32) return;
    int t = i >> 5, j = i & 31;
    double freq = pow(10000.0, -(double)j / 32.0);
    double ang = (double)t * freq;
    g_cos[i] = (float)cos(ang);
    g_sin[i] = (float)sin(ang);
}

// ===========================================================================
// tf32 mma.sync GEMM (inputs pre-rounded): C[m,n] = sum_k A[m,k]*B[n,k]
// 128x256x32 CTA tile, 8 warps (2x4), warp tile 64x64 (8 FLOP/smem-byte).
// 3-stage cp.async pipeline, one __syncthreads per chunk, 1 CTA/SM.
// MODE 0: row-major store. MODE 1: scatter to g_q/g_k/g_v [B,H,T,D] (round v).
// ===========================================================================
#define GEMM_SMEM_BYTES 147456   // 3 stages x (16KB A + 32KB B)

template <int MODE>
__global__ void __launch_bounds__(256, 1) gemm_mma(
    const float* __restrict__ A, const float* __restrict__ Bm,
    float* __restrict__ Cout, int M, int N, int K)
{
    extern __shared__ char smraw[];
    const uint32_t sb = smem_u32(smraw);
    const int tid = threadIdx.x;
    const int warp = tid >> 5, lane = tid & 31;
    const int wm = warp >> 2, wn = warp & 3;     // wm 0..1 (m64), wn 0..3 (n64)
    const int m0 = blockIdx.y * 128, n0 = blockIdx.x * 256;

    float acc[4][8][4];
#pragma unroll
    for (int i = 0; i < 4; i++)
#pragma unroll
        for (int j = 0; j < 8; j++)
#pragma unroll
            for (int q = 0; q < 4; q++) acc[i][j][q] = 0.f;

    const int nch = K / 32;

    auto load_chunk = [&](int c, int buf) {
        const int k0 = c * 32;
        const uint32_t abase = sb + buf * 49152;
        const uint32_t bbase = abase + 16384;
#pragma unroll
        for (int it = 0; it < 4; it++) {
            const int t = tid + it * 256;
            const int row = t >> 3, c4 = t & 7;
            CP_ASYNC16(abase + swz((uint32_t)(row * 128 + c4 * 16)),
                       A + (size_t)(m0 + row) * K + k0 + c4 * 4);
        }
#pragma unroll
        for (int it = 0; it < 8; it++) {
            const int t = tid + it * 256;
            const int row = t >> 3, c4 = t & 7;
            CP_ASYNC16(bbase + swz((uint32_t)(row * 128 + c4 * 16)),
                       Bm + (size_t)(n0 + row) * K + k0 + c4 * 4);
        }
    };

    load_chunk(0, 0); CP_COMMIT();
    load_chunk(1, 1); CP_COMMIT();

    const int sub = lane >> 3, r8 = lane & 7;

    for (int c = 0; c < nch; c++) {
        if (c + 1 < nch) { CP_WAIT1(); } else { CP_WAIT0(); }
        __syncthreads();
        if (c + 2 < nch) { load_chunk(c + 2, (c + 2) % 3); CP_COMMIT(); }

        const uint32_t abase = sb + (c % 3) * 49152;
        const uint32_t bbase = abase + 16384;

#pragma unroll
        for (int ks = 0; ks < 4; ks++) {
            uint32_t a[4][4], b[4][4];
#pragma unroll
            for (int mf = 0; mf < 4; mf++) {
                const int row = wm * 64 + mf * 16 + (sub & 1) * 8 + r8;
                const int kb = ks * 8 + (sub >> 1) * 4;
                LDMX4(a[mf], abase + swz((uint32_t)(row * 128 + kb * 4)));
            }
#pragma unroll
            for (int i = 0; i < 4; i++) {
                const int row = wn * 64 + i * 16 + (sub >> 1) * 8 + r8;
                const int kb = ks * 8 + (sub & 1) * 4;
                LDMX4(b[i], bbase + swz((uint32_t)(row * 128 + kb * 4)));
            }
#pragma unroll
            for (int mf = 0; mf < 4; mf++)
#pragma unroll
                for (int nf = 0; nf < 8; nf++) {
                    MMA_TF32(acc[mf][nf], a[mf][0], a[mf][1], a[mf][2], a[mf][3],
                             b[nf >> 1][(nf & 1) * 2], b[nf >> 1][(nf & 1) * 2 + 1]);
                }
        }
    }

    // epilogue
    const int g = lane >> 2, tig = lane & 3;
    if (MODE == 0) {
#pragma unroll
        for (int mf = 0; mf < 4; mf++) {
            const int mA = m0 + wm * 64 + mf * 16 + g;
#pragma unroll
            for (int nf = 0; nf < 8; nf++) {
                const int nn = n0 + wn * 64 + nf * 8 + tig * 2;
                *(float2*)(Cout + (size_t)mA * N + nn) =
                    make_float2(acc[mf][nf][0], acc[mf][nf][1]);
                *(float2*)(Cout + (size_t)(mA + 8) * N + nn) =
                    make_float2(acc[mf][nf][2], acc[mf][nf][3]);
            }
        }
    } else {
#pragma unroll
        for (int mf = 0; mf < 4; mf++) {
            const int mA = m0 + wm * 64 + mf * 16 + g;
            const int bA = mA >> 9, tA = mA & 511;
            const int mB = mA + 8;
            const int bB = mB >> 9, tB = mB & 511;
#pragma unroll
            for (int nf = 0; nf < 8; nf++) {
                const int n = n0 + wn * 64 + nf * 8 + tig * 2;
                const int which = n >> 11;
                const int h = (n & 2047) >> 7;
                const int d = n & 127;
                float* basep = (which == 0) ? g_q : (which == 1) ? g_k : g_v;
                float v0 = acc[mf][nf][0], v1 = acc[mf][nf][1];
                float v2 = acc[mf][nf][2], v3 = acc[mf][nf][3];
                if (which == 2) { v0 = rnaf(v0); v1 = rnaf(v1); v2 = rnaf(v2); v3 = rnaf(v3); }
                *(float2*)(basep + ((size_t)(bA * 16 + h) * 512 + tA) * 128 + d) =
                    make_float2(v0, v1);
                *(float2*)(basep + ((size_t)(bB * 16 + h) * 512 + tB) * 128 + d) =
                    make_float2(v2, v3);
            }
        }
    }
}

// ===========================================================================
// Tensor-core flash attention (unchanged from R4 — in-kernel rope + hi/lo).
// ===========================================================================
// smem word offsets
#define AQHI 0
#define AQLO 8448
#define AKHI 16896
#define AKLO 25344
#define AVS  33792          // stride 136
#define APS  42496          // 64 x 68
#define AMI  46848
#define ALI  46912
#define AAL  46976
#define APMX 47040          // [2][64]
#define APSM 47168          // [2][64]
#define ATTN_SMEM_FLOATS 47296
#define ATTN2_SMEM_BYTES (ATTN_SMEM_FLOATS * 4)

__global__ void __launch_bounds__(256, 1) attn_mma()
{
    extern __shared__ float sm[];
    const int tid = threadIdx.x;
    const int warp = tid >> 5, lane = tid & 31;
    const int wm = warp >> 1, wn = warp & 1;
    const int g = lane >> 2, tig = lane & 3;
    const int qt = blockIdx.x, hh = blockIdx.y, bb = blockIdx.z;
    const int bh = bb * 16 + hh, q0 = qt * 64;
    const int arow = wm * 16;

    const float* qbase = g_q + (size_t)bh * 512 * 128;
    const float* kbase = g_k + (size_t)bh * 512 * 128;
    const float* vbase = g_v + (size_t)bh * 512 * 128;
    const float scale = 0.08838834764831845f;   // 1/sqrt(128)

    // ---- stage Q: rope + scale + hi/lo split ----
#pragma unroll
    for (int it = 0; it < 8; it++) {
        const int p = tid + it * 256;
        const int row = p >> 5, j = p & 31;
        const int t = q0 + row;
        const float c = g_cos[t * 32 + j], s = g_sin[t * 32 + j];
        const float x1 = qbase[(size_t)t * 128 + j];
        const float x2 = qbase[(size_t)t * 128 + j + 32];
        const float r1 = (x1 * c - x2 * s) * scale;
        const float r2 = (x2 * c + x1 * s) * scale;
        const float h1 = rnaf(r1), h2 = rnaf(r2);
        sm[AQHI + row * 132 + j] = h1;      sm[AQLO + row * 132 + j] = rnaf(r1 - h1);
        sm[AQHI + row * 132 + j + 32] = h2; sm[AQLO + row * 132 + j + 32] = rnaf(r2 - h2);
    }
#pragma unroll
    for (int it = 0; it < 16; it++) {
        const int p = tid + it * 256;
        const int row = p >> 6, d = 64 + (p & 63);
        const float v = qbase[(size_t)(q0 + row) * 128 + d] * scale;
        const float hv = rnaf(v);
        sm[AQHI + row * 132 + d] = hv;
        sm[AQLO + row * 132 + d] = rnaf(v - hv);
    }
    if (tid < 64) { sm[AMI + tid] = -1e30f; sm[ALI + tid] = 0.f; }

    float o[8][4];
#pragma unroll
    for (int i = 0; i < 8; i++)
#pragma unroll
        for (int q = 0; q < 4; q++) o[i][q] = 0.f;

    for (int kt = 0; kt <= qt; kt++) {
        const int k0 = kt * 64;
        // ---- stage K (rope + split) and V ----
#pragma unroll
        for (int it = 0; it < 8; it++) {
            const int p = tid + it * 256;
            const int row = p >> 5, j = p & 31;
            const int t = k0 + row;
            const float c = g_cos[t * 32 + j], s = g_sin[t * 32 + j];
            const float x1 = kbase[(size_t)t * 128 + j];
            const float x2 = kbase[(size_t)t * 128 + j + 32];
            const float r1 = x1 * c - x2 * s;
            const float r2 = x2 * c + x1 * s;
            const float h1 = rnaf(r1), h2 = rnaf(r2);
            sm[AKHI + row * 132 + j] = h1;      sm[AKLO + row * 132 + j] = rnaf(r1 - h1);
            sm[AKHI + row * 132 + j + 32] = h2; sm[AKLO + row * 132 + j + 32] = rnaf(r2 - h2);
        }
#pragma unroll
        for (int it = 0; it < 16; it++) {
            const int p = tid + it * 256;
            const int row = p >> 6, d = 64 + (p & 63);
            const float v = kbase[(size_t)(k0 + row) * 128 + d];
            const float hv = rnaf(v);
            sm[AKHI + row * 132 + d] = hv;
            sm[AKLO + row * 132 + d] = rnaf(v - hv);
        }
#pragma unroll
        for (int it = 0; it < 8; it++) {
            const int p = tid + it * 256;
            const int row = p >> 5, c4 = (p & 31) * 4;
            *(float4*)&sm[AVS + row * 136 + c4] =
                *(const float4*)(vbase + (size_t)(k0 + row) * 128 + c4);
        }
        __syncthreads();

        // ---- S = Q K^T (3xTF32) ----
        float sacc[4][4];
#pragma unroll
        for (int nf = 0; nf < 4; nf++)
#pragma unroll
            for (int q = 0; q < 4; q++) sacc[nf][q] = 0.f;

#pragma unroll
        for (int dc = 0; dc < 16; dc++) {
            const int d0 = dc * 8;
            const int qiA = (arow + g) * 132 + d0 + tig;
            const int qiB = (arow + g + 8) * 132 + d0 + tig;
            uint32_t ah0 = U(sm[AQHI + qiA]);
            uint32_t ah1 = U(sm[AQHI + qiB]);
            uint32_t ah2 = U(sm[AQHI + qiA + 4]);
            uint32_t ah3 = U(sm[AQHI + qiB + 4]);
            uint32_t al0 = U(sm[AQLO + qiA]);
            uint32_t al1 = U(sm[AQLO + qiB]);
            uint32_t al2 = U(sm[AQLO + qiA + 4]);
            uint32_t al3 = U(sm[AQLO + qiB + 4]);
#pragma unroll
            for (int nf = 0; nf < 4; nf++) {
                const int kr = (wn * 32 + nf * 8 + g) * 132 + d0 + tig;
                uint32_t bh0 = U(sm[AKHI + kr]);
                uint32_t bh1 = U(sm[AKHI + kr + 4]);
                uint32_t bl0 = U(sm[AKLO + kr]);
                uint32_t bl1 = U(sm[AKLO + kr + 4]);
                MMA_TF32(sacc[nf], ah0, ah1, ah2, ah3, bh0, bh1);
                MMA_TF32(sacc[nf], ah0, ah1, ah2, ah3, bl0, bl1);
                MMA_TF32(sacc[nf], al0, al1, al2, al3, bh0, bh1);
            }
        }

        // ---- causal mask (diagonal tile only) ----
        if (kt == qt) {
            const int lrA = arow + g, lrB = lrA + 8;
#pragma unroll
            for (int nf = 0; nf < 4; nf++) {
                const int lc = wn * 32 + nf * 8 + 2 * tig;
                if (lc > lrA)     sacc[nf][0] = -1e30f;
                if (lc + 1 > lrA) sacc[nf][1] = -1e30f;
                if (lc > lrB)     sacc[nf][2] = -1e30f;
                if (lc + 1 > lrB) sacc[nf][3] = -1e30f;
            }
        }

        // ---- row max ----
        float mA = -1e30f, mB = -1e30f;
#pragma unroll
        for (int nf = 0; nf < 4; nf++) {
            mA = fmaxf(mA, fmaxf(sacc[nf][0], sacc[nf][1]));
            mB = fmaxf(mB, fmaxf(sacc[nf][2], sacc[nf][3]));
        }
        mA = fmaxf(mA, __shfl_xor_sync(0xffffffffu, mA, 1));
        mA = fmaxf(mA, __shfl_xor_sync(0xffffffffu, mA, 2));
        mB = fmaxf(mB, __shfl_xor_sync(0xffffffffu, mB, 1));
        mB = fmaxf(mB, __shfl_xor_sync(0xffffffffu, mB, 2));
        if (tig == 0) {
            sm[APMX + wn * 64 + arow + g] = mA;
            sm[APMX + wn * 64 + arow + g + 8] = mB;
        }
        __syncthreads();
        if (tid < 64) {
            const float mnew = fmaxf(sm[AMI + tid],
                                     fmaxf(sm[APMX + tid], sm[APMX + 64 + tid]));
            sm[AAL + tid] = __expf(sm[AMI + tid] - mnew);
            sm[AMI + tid] = mnew;
        }
        __syncthreads();

        // ---- p = exp(s - m), write P (rounded), row sums, rescale O ----
        const float mnA = sm[AMI + arow + g], mnB = sm[AMI + arow + g + 8];
        const float alA = sm[AAL + arow + g], alB = sm[AAL + arow + g + 8];
        float sumA = 0.f, sumB = 0.f;
#pragma unroll
        for (int nf = 0; nf < 4; nf++) {
            const float p0 = __expf(sacc[nf][0] - mnA);
            const float p1 = __expf(sacc[nf][1] - mnA);
            const float p2 = __expf(sacc[nf][2] - mnB);
            const float p3 = __expf(sacc[nf][3] - mnB);
            sumA += p0 + p1; sumB += p2 + p3;
            const int col = wn * 32 + nf * 8 + 2 * tig;
            *(float2*)&sm[APS + (arow + g) * 68 + col] = make_float2(rnaf(p0), rnaf(p1));
            *(float2*)&sm[APS + (arow + g + 8) * 68 + col] = make_float2(rnaf(p2), rnaf(p3));
        }
        sumA += __shfl_xor_sync(0xffffffffu, sumA, 1);
        sumA += __shfl_xor_sync(0xffffffffu, sumA, 2);
        sumB += __shfl_xor_sync(0xffffffffu, sumB, 1);
        sumB += __shfl_xor_sync(0xffffffffu, sumB, 2);
        if (tig == 0) {
            sm[APSM + wn * 64 + arow + g] = sumA;
            sm[APSM + wn * 64 + arow + g + 8] = sumB;
        }
#pragma unroll
        for (int nf2 = 0; nf2 < 8; nf2++) {
            o[nf2][0] *= alA; o[nf2][1] *= alA;
            o[nf2][2] *= alB; o[nf2][3] *= alB;
        }
        __syncthreads();
        if (tid < 64)
            sm[ALI + tid] = sm[ALI + tid] * sm[AAL + tid]
                          + sm[APSM + tid] + sm[APSM + 64 + tid];

        // ---- O += P @ V (tf32) ----
#pragma unroll
        for (int kc = 0; kc < 8; kc++) {
            const int piA = (arow + g) * 68 + kc * 8 + tig;
            const int piB = (arow + g + 8) * 68 + kc * 8 + tig;
            uint32_t a0 = U(sm[APS + piA]);
            uint32_t a1 = U(sm[APS + piB]);
            uint32_t a2 = U(sm[APS + piA + 4]);
            uint32_t a3 = U(sm[APS + piB + 4]);
#pragma unroll
            for (int nf2 = 0; nf2 < 8; nf2++) {
                const int d = wn * 64 + nf2 * 8 + g;
                uint32_t b0 = U(sm[AVS + (kc * 8 + tig) * 136 + d]);
                uint32_t b1 = U(sm[AVS + (kc * 8 + tig + 4) * 136 + d]);
                MMA_TF32(o[nf2], a0, a1, a2, a3, b0, b1);
            }
        }
        __syncthreads();
    }

    // ---- epilogue: normalize, round to tf32 (feeds gemm2), write g_y ----
    const float invA = 1.f / sm[ALI + arow + g];
    const float invB = 1.f / sm[ALI + arow + g + 8];
    const int tA = q0 + arow + g, tB = tA + 8;
#pragma unroll
    for (int nf2 = 0; nf2 < 8; nf2++) {
        const int d = wn * 64 + nf2 * 8 + 2 * tig;
        *(float2*)(g_y + ((size_t)bb * 512 + tA) * 2048 + hh * 128 + d) =
            make_float2(rnaf(o[nf2][0] * invA), rnaf(o[nf2][1] * invA));
        *(float2*)(g_y + ((size_t)bb * 512 + tB) * 2048 + hh * 128 + d) =
            make_float2(rnaf(o[nf2][2] * invB), rnaf(o[nf2][3] * invB));
    }
}

// ---------------------------------------------------------------------------
extern "C" void kernel_launch(void* const* d_in, const int* in_sizes, int n_in,
                              void* d_out, int out_size)
{
    (void)in_sizes; (void)n_in; (void)out_size;
    const float* x     = (const float*)d_in[0];
    const float* w_qkv = (const float*)d_in[1];
    const float* w_out = (const float*)d_in[2];
    float* out = (float*)d_out;

    float *y_ptr, *xr_ptr, *wqr_ptr, *wor_ptr;
    cudaGetSymbolAddress((void**)&y_ptr, g_y);
    cudaGetSymbolAddress((void**)&xr_ptr, g_xr);
    cudaGetSymbolAddress((void**)&wqr_ptr, g_wqr);
    cudaGetSymbolAddress((void**)&wor_ptr, g_wor);

    cudaFuncSetAttribute(gemm_mma<1>, cudaFuncAttributeMaxDynamicSharedMemorySize, GEMM_SMEM_BYTES);
    cudaFuncSetAttribute(gemm_mma<0>, cudaFuncAttributeMaxDynamicSharedMemorySize, GEMM_SMEM_BYTES);
    cudaFuncSetAttribute(attn_mma, cudaFuncAttributeMaxDynamicSharedMemorySize, ATTN2_SMEM_BYTES);

    // 0) pre-round inputs + rope tables
    round_tf32<<<(8388608 + 255) / 256, 256>>>(x, xr_ptr, 8388608);
    round_tf32<<<(3145728 + 255) / 256, 256>>>(w_qkv, wqr_ptr, 3145728);
    round_tf32<<<(1048576 + 255) / 256, 256>>>(w_out, wor_ptr, 1048576);
    build_tables<<<64, 256>>>();

    // 1) QKV projection (scatter to q/k/v; v rounded)
    {
        dim3 grid(6144 / 256, 16384 / 128);
        gemm_mma<1><<<grid, 256, GEMM_SMEM_BYTES>>>(xr_ptr, wqr_ptr, nullptr, 16384, 6144, 2048);
    }
    // 2) Attention (rope fused, tensor-core flash)
    {
        dim3 grid(8, 16, 32);
        attn_mma<<<grid, 256, ATTN2_SMEM_BYTES>>>();
    }
    // 3) Output projection
    {
        dim3 grid(2048 / 256, 16384 / 128);
        gemm_mma<0><<<grid, 256, GEMM_SMEM_BYTES>>>(y_ptr, wor_ptr, out, 16384, 2048, 2048);
    }
}

// round 8
// speedup vs baseline: 1.0995x; 1.0995x over previous
#include <cuda_runtime.h>
#include <math.h>
#include <cstdint>

// Shapes: x[32,512,2048] f32, w_qkv[6144,2048], w_out[2048,2048], out[32,512,2048]

// Scratch (device globals: allocation-free per harness rules)
__device__ float g_q[32L * 16 * 512 * 128];   // [B,H,T,D] fp32 pre-rope
__device__ float g_k[32L * 16 * 512 * 128];
__device__ float g_v[32L * 16 * 512 * 128];   // tf32-rounded at gemm epilogue
__device__ float g_y[32L * 512 * 2048];       // [B,T,C] attn out (tf32-rounded)
__device__ float g_xr[32L * 512 * 2048];      // tf32-rounded x
__device__ float g_wqr[6144L * 2048];         // tf32-rounded w_qkv
__device__ float g_wor[2048L * 2048];         // tf32-rounded w_out
__device__ float g_cos[512 * 32];
__device__ float g_sin[512 * 32];

// ===========================================================================
// Helpers
// ===========================================================================
__device__ __forceinline__ uint32_t smem_u32(const void* p) {
    uint32_t a;
    asm("{ .reg .u64 t; cvta.to.shared.u64 t, %1; cvt.u32.u64 %0, t; }" : "=r"(a) : "l"(p));
    return a;
}
__device__ __forceinline__ uint32_t swz(uint32_t off) { return off ^ ((off >> 3) & 0x70); }

#define CP_ASYNC16(dst, src) \
    asm volatile("cp.async.cg.shared.global [%0], [%1], 16;" :: "r"(dst), "l"(src))
#define CP_COMMIT() asm volatile("cp.async.commit_group;" ::: "memory")
#define CP_WAIT1() asm volatile("cp.async.wait_group 1;" ::: "memory")
#define CP_WAIT0() asm volatile("cp.async.wait_group 0;" ::: "memory")

__device__ __forceinline__ float rnaf(float x) {
    uint32_t r;
    asm("cvt.rna.tf32.f32 %0, %1;" : "=r"(r) : "f"(x));
    return __uint_as_float(r);
}
__device__ __forceinline__ uint32_t U(float x) { return __float_as_uint(x); }

#define MMA_TF32(c, A0, A1, A2, A3, B0, B1) \
    asm volatile("mma.sync.aligned.m16n8k8.row.col.f32.tf32.tf32.f32 " \
        "{%0,%1,%2,%3},{%4,%5,%6,%7},{%8,%9},{%0,%1,%2,%3};" \
        : "+f"((c)[0]), "+f"((c)[1]), "+f"((c)[2]), "+f"((c)[3]) \
        : "r"(A0), "r"(A1), "r"(A2), "r"(A3), "r"(B0), "r"(B1))

#define LDMX4(r, addr) \
    asm volatile("ldmatrix.sync.aligned.m8n8.x4.shared.b16 {%0,%1,%2,%3}, [%4];" \
        : "=r"((r)[0]), "=r"((r)[1]), "=r"((r)[2]), "=r"((r)[3]) : "r"(addr))

// ===========================================================================
// elementwise tf32-round (RNA)
// ===========================================================================
__global__ void round_tf32(const float* __restrict__ in, float* __restrict__ out, int n4)
{
    int i = blockIdx.x * blockDim.x + threadIdx.x;
    if (i >= n4) return;
    float4 v = ((const float4*)in)[i];
    v.x = rnaf(v.x); v.y = rnaf(v.y); v.z = rnaf(v.z); v.w = rnaf(v.w);
    ((float4*)out)[i] = v;
}

// rope tables (double-precision build, matches numpy float64 path)
__global__ void build_tables()
{
    int i = blockIdx.x * blockDim.x + threadIdx.x;
    if (i >= 512 * 32) return;
    int t = i >> 5, j = i & 31;
    double freq = pow(10000.0, -(double)j / 32.0);
    double ang = (double)t * freq;
    g_cos[i] = (float)cos(ang);
    g_sin[i] = (float)sin(ang);
}

// ===========================================================================
// tf32 mma.sync GEMM — EXACT R4 config (best known): 128x128x32 tile,
// 8 warps (2x4), warp 64x32, 2-stage cp.async, 2 CTA/SM.
// MODE 0: row-major store. MODE 1: scatter to g_q/g_k/g_v [B,H,T,D] (round v).
// ===========================================================================
#define GEMM_SMEM_BYTES 65536   // 2 bufs x (16KB A + 16KB B)

template <int MODE>
__global__ void __launch_bounds__(256, 2) gemm_mma(
    const float* __restrict__ A, const float* __restrict__ Bm,
    float* __restrict__ Cout, int M, int N, int K)
{
    extern __shared__ char smraw[];
    const uint32_t sb = smem_u32(smraw);
    const int tid = threadIdx.x;
    const int warp = tid >> 5, lane = tid & 31;
    const int wm = warp >> 2, wn = warp & 3;
    const int m0 = blockIdx.y * 128, n0 = blockIdx.x * 128;

    float acc[4][4][4];
#pragma unroll
    for (int i = 0; i < 4; i++)
#pragma unroll
        for (int j = 0; j < 4; j++)
#pragma unroll
            for (int q = 0; q < 4; q++) acc[i][j][q] = 0.f;

    const int nch = K / 32;

    auto load_chunk = [&](int c, int buf) {
        const int k0 = c * 32;
        const uint32_t abase = sb + buf * 32768;
        const uint32_t bbase = abase + 16384;
#pragma unroll
        for (int it = 0; it < 4; it++) {
            const int t = tid + it * 256;
            const int row = t >> 3, c4 = t & 7;
            CP_ASYNC16(abase + swz((uint32_t)(row * 128 + c4 * 16)),
                       A + (size_t)(m0 + row) * K + k0 + c4 * 4);
        }
#pragma unroll
        for (int it = 0; it < 4; it++) {
            const int t = tid + it * 256;
            const int row = t >> 3, c4 = t & 7;
            CP_ASYNC16(bbase + swz((uint32_t)(row * 128 + c4 * 16)),
                       Bm + (size_t)(n0 + row) * K + k0 + c4 * 4);
        }
    };

    load_chunk(0, 0);
    CP_COMMIT();

    const int sub = lane >> 3, r8 = lane & 7;

    for (int c = 0; c < nch; c++) {
        const int buf = c & 1;
        const bool has_next = (c + 1 < nch);
        if (has_next) {
            load_chunk(c + 1, (c + 1) & 1);
            CP_COMMIT();
            CP_WAIT1();
        } else {
            CP_WAIT0();
        }
        __syncthreads();

        const uint32_t abase = sb + buf * 32768;
        const uint32_t bbase = abase + 16384;

#pragma unroll
        for (int ks = 0; ks < 4; ks++) {
            uint32_t a[4][4], b[2][4];
#pragma unroll
            for (int mf = 0; mf < 4; mf++) {
                const int row = wm * 64 + mf * 16 + (sub & 1) * 8 + r8;
                const int kb = ks * 8 + (sub >> 1) * 4;
                LDMX4(a[mf], abase + swz((uint32_t)(row * 128 + kb * 4)));
            }
#pragma unroll
            for (int i = 0; i < 2; i++) {
                const int row = wn * 32 + i * 16 + (sub >> 1) * 8 + r8;
                const int kb = ks * 8 + (sub & 1) * 4;
                LDMX4(b[i], bbase + swz((uint32_t)(row * 128 + kb * 4)));
            }
#pragma unroll
            for (int mf = 0; mf < 4; mf++)
#pragma unroll
                for (int nf = 0; nf < 4; nf++) {
                    MMA_TF32(acc[mf][nf], a[mf][0], a[mf][1], a[mf][2], a[mf][3],
                             b[nf >> 1][(nf & 1) * 2], b[nf >> 1][(nf & 1) * 2 + 1]);
                }
        }
        __syncthreads();
    }

    // epilogue
    const int g = lane >> 2, tig = lane & 3;
    if (MODE == 0) {
#pragma unroll
        for (int mf = 0; mf < 4; mf++) {
            const int mA = m0 + wm * 64 + mf * 16 + g;
#pragma unroll
            for (int nf = 0; nf < 4; nf++) {
                const int nn = n0 + wn * 32 + nf * 8 + tig * 2;
                *(float2*)(Cout + (size_t)mA * N + nn) =
                    make_float2(acc[mf][nf][0], acc[mf][nf][1]);
                *(float2*)(Cout + (size_t)(mA + 8) * N + nn) =
                    make_float2(acc[mf][nf][2], acc[mf][nf][3]);
            }
        }
    } else {
        const int which = n0 >> 11;
        const int h = (n0 & 2047) >> 7;
        float* basep = (which == 0) ? g_q : (which == 1) ? g_k : g_v;
        const bool doround = (which == 2);
#pragma unroll
        for (int mf = 0; mf < 4; mf++) {
            const int mA = m0 + wm * 64 + mf * 16 + g;
            const int bA = mA >> 9, tA = mA & 511;
            const int mB = mA + 8;
            const int bB = mB >> 9, tB = mB & 511;
#pragma unroll
            for (int nf = 0; nf < 4; nf++) {
                const int d = wn * 32 + nf * 8 + tig * 2;
                float v0 = acc[mf][nf][0], v1 = acc[mf][nf][1];
                float v2 = acc[mf][nf][2], v3 = acc[mf][nf][3];
                if (doround) { v0 = rnaf(v0); v1 = rnaf(v1); v2 = rnaf(v2); v3 = rnaf(v3); }
                *(float2*)(basep + ((size_t)(bA * 16 + h) * 512 + tA) * 128 + d) =
                    make_float2(v0, v1);
                *(float2*)(basep + ((size_t)(bB * 16 + h) * 512 + tB) * 128 + d) =
                    make_float2(v2, v3);
            }
        }
    }
}

// ===========================================================================
// Tensor-core flash attention — single-pass tf32 QK^T (no hi/lo split).
// Block = (64 q-rows, one (b,h)). 8 warps: wm 0..3 (16 q-rows), wn 0..1.
// Q/K staged roped + RNA-rounded; fragments via ldmatrix (mapping validated R5).
// ===========================================================================
// smem word offsets
#define SQ  0               // 64 x 132
#define SK  8448            // 64 x 132
#define SV  16896           // 64 x 136
#define SP  25600           // 64 x 68
#define AMI 29952
#define ALI 30016
#define AAL 30080
#define APMX 30144          // [2][64]
#define APSM 30272          // [2][64]
#define ATTN_SMEM_FLOATS 30400
#define ATTN2_SMEM_BYTES (ATTN_SMEM_FLOATS * 4)

__global__ void __launch_bounds__(256, 1) attn_mma()
{
    extern __shared__ float sm[];
    const uint32_t sb = smem_u32(sm);
    const int tid = threadIdx.x;
    const int warp = tid >> 5, lane = tid & 31;
    const int wm = warp >> 1, wn = warp & 1;
    const int g = lane >> 2, tig = lane & 3;
    const int sub = lane >> 3, r8 = lane & 7;
    const int qt = blockIdx.x, hh = blockIdx.y, bb = blockIdx.z;
    const int bh = bb * 16 + hh, q0 = qt * 64;
    const int arow = wm * 16;
    const int frow = (sub & 1) * 8 + r8;       // A-fragment row offset
    const int fcol = (sub >> 1) * 4;           // A-fragment col offset
    const int brow = (sub >> 1) * 8 + r8;      // B-fragment row offset
    const int bcol = (sub & 1) * 4;            // B-fragment col offset

    const float* qbase = g_q + (size_t)bh * 512 * 128;
    const float* kbase = g_k + (size_t)bh * 512 * 128;
    const float* vbase = g_v + (size_t)bh * 512 * 128;
    const float scale = 0.08838834764831845f;   // 1/sqrt(128)

    // ---- stage Q: rope + scale + tf32 round ----
#pragma unroll
    for (int it = 0; it < 8; it++) {
        const int p = tid + it * 256;
        const int row = p >> 5, j = p & 31;
        const int t = q0 + row;
        const float c = g_cos[t * 32 + j], s = g_sin[t * 32 + j];
        const float x1 = qbase[(size_t)t * 128 + j];
        const float x2 = qbase[(size_t)t * 128 + j + 32];
        sm[SQ + row * 132 + j]      = rnaf((x1 * c - x2 * s) * scale);
        sm[SQ + row * 132 + j + 32] = rnaf((x2 * c + x1 * s) * scale);
    }
#pragma unroll
    for (int it = 0; it < 16; it++) {
        const int p = tid + it * 256;
        const int row = p >> 6, d = 64 + (p & 63);
        sm[SQ + row * 132 + d] = rnaf(qbase[(size_t)(q0 + row) * 128 + d] * scale);
    }
    if (tid < 64) { sm[AMI + tid] = -1e30f; sm[ALI + tid] = 0.f; }

    float o[8][4];
#pragma unroll
    for (int i = 0; i < 8; i++)
#pragma unroll
        for (int q = 0; q < 4; q++) o[i][q] = 0.f;

    for (int kt = 0; kt <= qt; kt++) {
        const int k0 = kt * 64;
        // ---- stage K (rope + round) and V ----
#pragma unroll
        for (int it = 0; it < 8; it++) {
            const int p = tid + it * 256;
            const int row = p >> 5, j = p & 31;
            const int t = k0 + row;
            const float c = g_cos[t * 32 + j], s = g_sin[t * 32 + j];
            const float x1 = kbase[(size_t)t * 128 + j];
            const float x2 = kbase[(size_t)t * 128 + j + 32];
            sm[SK + row * 132 + j]      = rnaf(x1 * c - x2 * s);
            sm[SK + row * 132 + j + 32] = rnaf(x2 * c + x1 * s);
        }
#pragma unroll
        for (int it = 0; it < 16; it++) {
            const int p = tid + it * 256;
            const int row = p >> 6, d = 64 + (p & 63);
            sm[SK + row * 132 + d] = rnaf(kbase[(size_t)(k0 + row) * 128 + d]);
        }
#pragma unroll
        for (int it = 0; it < 8; it++) {
            const int p = tid + it * 256;
            const int row = p >> 5, c4 = (p & 31) * 4;
            *(float4*)&sm[SV + row * 136 + c4] =
                *(const float4*)(vbase + (size_t)(k0 + row) * 128 + c4);
        }
        __syncthreads();

        // ---- S = Q K^T (single tf32, ldmatrix fragments) ----
        float sacc[4][4];
#pragma unroll
        for (int nf = 0; nf < 4; nf++)
#pragma unroll
            for (int q = 0; q < 4; q++) sacc[nf][q] = 0.f;

#pragma unroll
        for (int dc = 0; dc < 16; dc++) {
            const int d0 = dc * 8;
            uint32_t a[4];
            LDMX4(a, sb + (SQ + (arow + frow) * 132 + d0 + fcol) * 4);
#pragma unroll
            for (int nfp = 0; nfp < 2; nfp++) {
                uint32_t bf[4];
                const int krow = wn * 32 + nfp * 16 + brow;
                LDMX4(bf, sb + (SK + krow * 132 + d0 + bcol) * 4);
#pragma unroll
                for (int i = 0; i < 2; i++) {
                    const int nf = nfp * 2 + i;
                    MMA_TF32(sacc[nf], a[0], a[1], a[2], a[3],
                             bf[i * 2], bf[i * 2 + 1]);
                }
            }
        }

        // ---- causal mask (diagonal tile only) ----
        if (kt == qt) {
            const int lrA = arow + g, lrB = lrA + 8;
#pragma unroll
            for (int nf = 0; nf < 4; nf++) {
                const int lc = wn * 32 + nf * 8 + 2 * tig;
                if (lc > lrA)     sacc[nf][0] = -1e30f;
                if (lc + 1 > lrA) sacc[nf][1] = -1e30f;
                if (lc > lrB)     sacc[nf][2] = -1e30f;
                if (lc + 1 > lrB) sacc[nf][3] = -1e30f;
            }
        }

        // ---- row max ----
        float mA = -1e30f, mB = -1e30f;
#pragma unroll
        for (int nf = 0; nf < 4; nf++) {
            mA = fmaxf(mA, fmaxf(sacc[nf][0], sacc[nf][1]));
            mB = fmaxf(mB, fmaxf(sacc[nf][2], sacc[nf][3]));
        }
        mA = fmaxf(mA, __shfl_xor_sync(0xffffffffu, mA, 1));
        mA = fmaxf(mA, __shfl_xor_sync(0xffffffffu, mA, 2));
        mB = fmaxf(mB, __shfl_xor_sync(0xffffffffu, mB, 1));
        mB = fmaxf(mB, __shfl_xor_sync(0xffffffffu, mB, 2));
        if (tig == 0) {
            sm[APMX + wn * 64 + arow + g] = mA;
            sm[APMX + wn * 64 + arow + g + 8] = mB;
        }
        __syncthreads();
        if (tid < 64) {
            const float mnew = fmaxf(sm[AMI + tid],
                                     fmaxf(sm[APMX + tid], sm[APMX + 64 + tid]));
            sm[AAL + tid] = __expf(sm[AMI + tid] - mnew);
            sm[AMI + tid] = mnew;
        }
        __syncthreads();

        // ---- p = exp(s - m), write P (rounded), row sums, rescale O ----
        const float mnA = sm[AMI + arow + g], mnB = sm[AMI + arow + g + 8];
        const float alA = sm[AAL + arow + g], alB = sm[AAL + arow + g + 8];
        float sumA = 0.f, sumB = 0.f;
#pragma unroll
        for (int nf = 0; nf < 4; nf++) {
            const float p0 = __expf(sacc[nf][0] - mnA);
            const float p1 = __expf(sacc[nf][1] - mnA);
            const float p2 = __expf(sacc[nf][2] - mnB);
            const float p3 = __expf(sacc[nf][3] - mnB);
            sumA += p0 + p1; sumB += p2 + p3;
            const int col = wn * 32 + nf * 8 + 2 * tig;
            *(float2*)&sm[SP + (arow + g) * 68 + col] = make_float2(rnaf(p0), rnaf(p1));
            *(float2*)&sm[SP + (arow + g + 8) * 68 + col] = make_float2(rnaf(p2), rnaf(p3));
        }
        sumA += __shfl_xor_sync(0xffffffffu, sumA, 1);
        sumA += __shfl_xor_sync(0xffffffffu, sumA, 2);
        sumB += __shfl_xor_sync(0xffffffffu, sumB, 1);
        sumB += __shfl_xor_sync(0xffffffffu, sumB, 2);
        if (tig == 0) {
            sm[APSM + wn * 64 + arow + g] = sumA;
            sm[APSM + wn * 64 + arow + g + 8] = sumB;
        }
#pragma unroll
        for (int nf2 = 0; nf2 < 8; nf2++) {
            o[nf2][0] *= alA; o[nf2][1] *= alA;
            o[nf2][2] *= alB; o[nf2][3] *= alB;
        }
        __syncthreads();
        if (tid < 64)
            sm[ALI + tid] = sm[ALI + tid] * sm[AAL + tid]
                          + sm[APSM + tid] + sm[APSM + 64 + tid];

        // ---- O += P @ V (tf32, P via ldmatrix, V scalar) ----
#pragma unroll
        for (int kc = 0; kc < 8; kc++) {
            uint32_t a[4];
            LDMX4(a, sb + (SP + (arow + frow) * 68 + kc * 8 + fcol) * 4);
#pragma unroll
            for (int nf2 = 0; nf2 < 8; nf2++) {
                const int d = wn * 64 + nf2 * 8 + g;
                const uint32_t b0 = U(sm[SV + (kc * 8 + tig) * 136 + d]);
                const uint32_t b1 = U(sm[SV + (kc * 8 + tig + 4) * 136 + d]);
                MMA_TF32(o[nf2], a[0], a[1], a[2], a[3], b0, b1);
            }
        }
        __syncthreads();
    }

    // ---- epilogue: normalize, round to tf32 (feeds gemm2), write g_y ----
    const float invA = 1.f / sm[ALI + arow + g];
    const float invB = 1.f / sm[ALI + arow + g + 8];
    const int tA = q0 + arow + g, tB = tA + 8;
#pragma unroll
    for (int nf2 = 0; nf2 < 8; nf2++) {
        const int d = wn * 64 + nf2 * 8 + 2 * tig;
        *(float2*)(g_y + ((size_t)bb * 512 + tA) * 2048 + hh * 128 + d) =
            make_float2(rnaf(o[nf2][0] * invA), rnaf(o[nf2][1] * invA));
        *(float2*)(g_y + ((size_t)bb * 512 + tB) * 2048 + hh * 128 + d) =
            make_float2(rnaf(o[nf2][2] * invB), rnaf(o[nf2][3] * invB));
    }
}

// ---------------------------------------------------------------------------
extern "C" void kernel_launch(void* const* d_in, const int* in_sizes, int n_in,
                              void* d_out, int out_size)
{
    (void)in_sizes; (void)n_in; (void)out_size;
    const float* x     = (const float*)d_in[0];
    const float* w_qkv = (const float*)d_in[1];
    const float* w_out = (const float*)d_in[2];
    float* out = (float*)d_out;

    float *y_ptr, *xr_ptr, *wqr_ptr, *wor_ptr;
    cudaGetSymbolAddress((void**)&y_ptr, g_y);
    cudaGetSymbolAddress((void**)&xr_ptr, g_xr);
    cudaGetSymbolAddress((void**)&wqr_ptr, g_wqr);
    cudaGetSymbolAddress((void**)&wor_ptr, g_wor);

    cudaFuncSetAttribute(gemm_mma<1>, cudaFuncAttributeMaxDynamicSharedMemorySize, GEMM_SMEM_BYTES);
    cudaFuncSetAttribute(gemm_mma<0>, cudaFuncAttributeMaxDynamicSharedMemorySize, GEMM_SMEM_BYTES);
    cudaFuncSetAttribute(attn_mma, cudaFuncAttributeMaxDynamicSharedMemorySize, ATTN2_SMEM_BYTES);

    // 0) pre-round inputs + rope tables
    round_tf32<<<(8388608 + 255) / 256, 256>>>(x, xr_ptr, 8388608);
    round_tf32<<<(3145728 + 255) / 256, 256>>>(w_qkv, wqr_ptr, 3145728);
    round_tf32<<<(1048576 + 255) / 256, 256>>>(w_out, wor_ptr, 1048576);
    build_tables<<<64, 256>>>();

    // 1) QKV projection (scatter to q/k/v; v rounded)
    {
        dim3 grid(6144 / 128, 16384 / 128);
        gemm_mma<1><<<grid, 256, GEMM_SMEM_BYTES>>>(xr_ptr, wqr_ptr, nullptr, 16384, 6144, 2048);
    }
    // 2) Attention (rope fused, tensor-core flash, single-tf32 QK^T)
    {
        dim3 grid(8, 16, 32);
        attn_mma<<<grid, 256, ATTN2_SMEM_BYTES>>>();
    }
    // 3) Output projection
    {
        dim3 grid(2048 / 128, 16384 / 128);
        gemm_mma<0><<<grid, 256, GEMM_SMEM_BYTES>>>(y_ptr, wor_ptr, out, 16384, 2048, 2048);
    }
}

// round 9
// speedup vs baseline: 1.1012x; 1.0015x over previous
#include <cuda_runtime.h>
#include <math.h>
#include <cstdint>

// Shapes: x[32,512,2048] f32, w_qkv[6144,2048], w_out[2048,2048], out[32,512,2048]

// Scratch (device globals: allocation-free per harness rules)
__device__ float g_q[32L * 16 * 512 * 128];   // [B,H,T,D]; after rope_round: roped+scaled+tf32
__device__ float g_k[32L * 16 * 512 * 128];   // after rope_round: roped+tf32
__device__ float g_v[32L * 16 * 512 * 128];   // tf32-rounded at gemm epilogue
__device__ float g_y[32L * 512 * 2048];       // [B,T,C] attn out (tf32-rounded)
__device__ float g_xr[32L * 512 * 2048];      // tf32-rounded x
__device__ float g_wqr[6144L * 2048];         // tf32-rounded w_qkv
__device__ float g_wor[2048L * 2048];         // tf32-rounded w_out
__device__ float g_cos[512 * 32];
__device__ float g_sin[512 * 32];

// ===========================================================================
// Helpers
// ===========================================================================
__device__ __forceinline__ uint32_t smem_u32(const void* p) {
    uint32_t a;
    asm("{ .reg .u64 t; cvta.to.shared.u64 t, %1; cvt.u32.u64 %0, t; }" : "=r"(a) : "l"(p));
    return a;
}
__device__ __forceinline__ uint32_t swz(uint32_t off) { return off ^ ((off >> 3) & 0x70); }

#define CP_ASYNC16(dst, src) \
    asm volatile("cp.async.cg.shared.global [%0], [%1], 16;" :: "r"(dst), "l"(src))
#define CP_COMMIT() asm volatile("cp.async.commit_group;" ::: "memory")
#define CP_WAIT1() asm volatile("cp.async.wait_group 1;" ::: "memory")
#define CP_WAIT0() asm volatile("cp.async.wait_group 0;" ::: "memory")

__device__ __forceinline__ float rnaf(float x) {
    uint32_t r;
    asm("cvt.rna.tf32.f32 %0, %1;" : "=r"(r) : "f"(x));
    return __uint_as_float(r);
}
__device__ __forceinline__ uint32_t U(float x) { return __float_as_uint(x); }

#define MMA_TF32(c, A0, A1, A2, A3, B0, B1) \
    asm volatile("mma.sync.aligned.m16n8k8.row.col.f32.tf32.tf32.f32 " \
        "{%0,%1,%2,%3},{%4,%5,%6,%7},{%8,%9},{%0,%1,%2,%3};" \
        : "+f"((c)[0]), "+f"((c)[1]), "+f"((c)[2]), "+f"((c)[3]) \
        : "r"(A0), "r"(A1), "r"(A2), "r"(A3), "r"(B0), "r"(B1))

#define LDMX4(r, addr) \
    asm volatile("ldmatrix.sync.aligned.m8n8.x4.shared.b16 {%0,%1,%2,%3}, [%4];" \
        : "=r"((r)[0]), "=r"((r)[1]), "=r"((r)[2]), "=r"((r)[3]) : "r"(addr))

// ===========================================================================
// elementwise tf32-round (RNA)
// ===========================================================================
__global__ void round_tf32(const float* __restrict__ in, float* __restrict__ out, int n4)
{
    int i = blockIdx.x * blockDim.x + threadIdx.x;
    if (i >= n4) return;
    float4 v = ((const float4*)in)[i];
    v.x = rnaf(v.x); v.y = rnaf(v.y); v.z = rnaf(v.z); v.w = rnaf(v.w);
    ((float4*)out)[i] = v;
}

// rope tables (double-precision build, matches numpy float64 path)
__global__ void build_tables()
{
    int i = blockIdx.x * blockDim.x + threadIdx.x;
    if (i >= 512 * 32) return;
    int t = i >> 5, j = i & 31;
    double freq = pow(10000.0, -(double)j / 32.0);
    double ang = (double)t * freq;
    g_cos[i] = (float)cos(ang);
    g_sin[i] = (float)sin(ang);
}

// ===========================================================================
// In-place rope + scale + tf32-round of q; rope + round of k.
// Block 256 threads = 4 rows (64 thr/row). Grid (128 t-groups, 512 bh, 2 sel).
// Each thread exclusively owns its elements -> race-free in-place.
// Values are bit-identical to R8's in-attention staging.
// ===========================================================================
__global__ void __launch_bounds__(256) rope_round()
{
    const int tid = threadIdx.x;
    const int s = tid & 63;
    const int t = blockIdx.x * 4 + (tid >> 6);
    const int bh = blockIdx.y;
    const int sel = blockIdx.z;
    float* p = (sel ? g_k : g_q) + ((size_t)bh * 512 + t) * 128;
    const float scale = sel ? 1.0f : 0.08838834764831845f;

    if (s < 32) {
        const float c = g_cos[t * 32 + s], si = g_sin[t * 32 + s];
        const float x1 = p[s], x2 = p[s + 32];
        p[s]      = rnaf((x1 * c - x2 * si) * scale);
        p[s + 32] = rnaf((x2 * c + x1 * si) * scale);
    } else {
        const int d1 = s + 32, d2 = s + 64;
        p[d1] = rnaf(p[d1] * scale);
        p[d2] = rnaf(p[d2] * scale);
    }
}

// ===========================================================================
// tf32 mma.sync GEMM — EXACT R4 config (best known): 128x128x32 tile,
// 8 warps (2x4), warp 64x32, 2-stage cp.async, 2 CTA/SM.
// MODE 0: row-major store. MODE 1: scatter to g_q/g_k/g_v [B,H,T,D] (round v).
// ===========================================================================
#define GEMM_SMEM_BYTES 65536   // 2 bufs x (16KB A + 16KB B)

template <int MODE>
__global__ void __launch_bounds__(256, 2) gemm_mma(
    const float* __restrict__ A, const float* __restrict__ Bm,
    float* __restrict__ Cout, int M, int N, int K)
{
    extern __shared__ char smraw[];
    const uint32_t sb = smem_u32(smraw);
    const int tid = threadIdx.x;
    const int warp = tid >> 5, lane = tid & 31;
    const int wm = warp >> 2, wn = warp & 3;
    const int m0 = blockIdx.y * 128, n0 = blockIdx.x * 128;

    float acc[4][4][4];
#pragma unroll
    for (int i = 0; i < 4; i++)
#pragma unroll
        for (int j = 0; j < 4; j++)
#pragma unroll
            for (int q = 0; q < 4; q++) acc[i][j][q] = 0.f;

    const int nch = K / 32;

    auto load_chunk = [&](int c, int buf) {
        const int k0 = c * 32;
        const uint32_t abase = sb + buf * 32768;
        const uint32_t bbase = abase + 16384;
#pragma unroll
        for (int it = 0; it < 4; it++) {
            const int t = tid + it * 256;
            const int row = t >> 3, c4 = t & 7;
            CP_ASYNC16(abase + swz((uint32_t)(row * 128 + c4 * 16)),
                       A + (size_t)(m0 + row) * K + k0 + c4 * 4);
        }
#pragma unroll
        for (int it = 0; it < 4; it++) {
            const int t = tid + it * 256;
            const int row = t >> 3, c4 = t & 7;
            CP_ASYNC16(bbase + swz((uint32_t)(row * 128 + c4 * 16)),
                       Bm + (size_t)(n0 + row) * K + k0 + c4 * 4);
        }
    };

    load_chunk(0, 0);
    CP_COMMIT();

    const int sub = lane >> 3, r8 = lane & 7;

    for (int c = 0; c < nch; c++) {
        const int buf = c & 1;
        const bool has_next = (c + 1 < nch);
        if (has_next) {
            load_chunk(c + 1, (c + 1) & 1);
            CP_COMMIT();
            CP_WAIT1();
        } else {
            CP_WAIT0();
        }
        __syncthreads();

        const uint32_t abase = sb + buf * 32768;
        const uint32_t bbase = abase + 16384;

#pragma unroll
        for (int ks = 0; ks < 4; ks++) {
            uint32_t a[4][4], b[2][4];
#pragma unroll
            for (int mf = 0; mf < 4; mf++) {
                const int row = wm * 64 + mf * 16 + (sub & 1) * 8 + r8;
                const int kb = ks * 8 + (sub >> 1) * 4;
                LDMX4(a[mf], abase + swz((uint32_t)(row * 128 + kb * 4)));
            }
#pragma unroll
            for (int i = 0; i < 2; i++) {
                const int row = wn * 32 + i * 16 + (sub >> 1) * 8 + r8;
                const int kb = ks * 8 + (sub & 1) * 4;
                LDMX4(b[i], bbase + swz((uint32_t)(row * 128 + kb * 4)));
            }
#pragma unroll
            for (int mf = 0; mf < 4; mf++)
#pragma unroll
                for (int nf = 0; nf < 4; nf++) {
                    MMA_TF32(acc[mf][nf], a[mf][0], a[mf][1], a[mf][2], a[mf][3],
                             b[nf >> 1][(nf & 1) * 2], b[nf >> 1][(nf & 1) * 2 + 1]);
                }
        }
        __syncthreads();
    }

    // epilogue
    const int g = lane >> 2, tig = lane & 3;
    if (MODE == 0) {
#pragma unroll
        for (int mf = 0; mf < 4; mf++) {
            const int mA = m0 + wm * 64 + mf * 16 + g;
#pragma unroll
            for (int nf = 0; nf < 4; nf++) {
                const int nn = n0 + wn * 32 + nf * 8 + tig * 2;
                *(float2*)(Cout + (size_t)mA * N + nn) =
                    make_float2(acc[mf][nf][0], acc[mf][nf][1]);
                *(float2*)(Cout + (size_t)(mA + 8) * N + nn) =
                    make_float2(acc[mf][nf][2], acc[mf][nf][3]);
            }
        }
    } else {
        const int which = n0 >> 11;
        const int h = (n0 & 2047) >> 7;
        float* basep = (which == 0) ? g_q : (which == 1) ? g_k : g_v;
        const bool doround = (which == 2);
#pragma unroll
        for (int mf = 0; mf < 4; mf++) {
            const int mA = m0 + wm * 64 + mf * 16 + g;
            const int bA = mA >> 9, tA = mA & 511;
            const int mB = mA + 8;
            const int bB = mB >> 9, tB = mB & 511;
#pragma unroll
            for (int nf = 0; nf < 4; nf++) {
                const int d = wn * 32 + nf * 8 + tig * 2;
                float v0 = acc[mf][nf][0], v1 = acc[mf][nf][1];
                float v2 = acc[mf][nf][2], v3 = acc[mf][nf][3];
                if (doround) { v0 = rnaf(v0); v1 = rnaf(v1); v2 = rnaf(v2); v3 = rnaf(v3); }
                *(float2*)(basep + ((size_t)(bA * 16 + h) * 512 + tA) * 128 + d) =
                    make_float2(v0, v1);
                *(float2*)(basep + ((size_t)(bB * 16 + h) * 512 + tB) * 128 + d) =
                    make_float2(v2, v3);
            }
        }
    }
}

// ===========================================================================
// Tensor-core flash attention — pure cp.async staging (q/k pre-roped+rounded),
// double-buffered K/V prefetch. 8 warps: wm 0..3 (16 q-rows), wn 0..1.
// ===========================================================================
// smem word offsets
#define SQ  0                      // 64 x 132
#define SKB(b) (8448 + (b) * 8448) // two K bufs, 64 x 132
#define SVB(b) (25344 + (b) * 8704)// two V bufs, 64 x 136
#define SP  42752                  // 64 x 68
#define AMI 47104
#define ALI 47168
#define AAL 47232
#define APMX 47296                 // [2][64]
#define APSM 47424                 // [2][64]
#define ATTN_SMEM_FLOATS 47552
#define ATTN2_SMEM_BYTES (ATTN_SMEM_FLOATS * 4)   // 190,208 B

__global__ void __launch_bounds__(256, 1) attn_mma()
{
    extern __shared__ float sm[];
    const uint32_t sb = smem_u32(sm);
    const int tid = threadIdx.x;
    const int warp = tid >> 5, lane = tid & 31;
    const int wm = warp >> 1, wn = warp & 1;
    const int g = lane >> 2, tig = lane & 3;
    const int sub = lane >> 3, r8 = lane & 7;
    const int qt = blockIdx.x, hh = blockIdx.y, bb = blockIdx.z;
    const int bh = bb * 16 + hh, q0 = qt * 64;
    const int arow = wm * 16;
    const int frow = (sub & 1) * 8 + r8;       // A-fragment row offset
    const int fcol = (sub >> 1) * 4;           // A-fragment col offset
    const int brow = (sub >> 1) * 8 + r8;      // B-fragment row offset
    const int bcol = (sub & 1) * 4;            // B-fragment col offset

    const float* qbase = g_q + (size_t)bh * 512 * 128;
    const float* kbase = g_k + (size_t)bh * 512 * 128;
    const float* vbase = g_v + (size_t)bh * 512 * 128;

    // cp.async 64x128 tile into padded smem
    auto stage = [&](uint32_t dstw, int stridew, const float* src) {
#pragma unroll
        for (int it = 0; it < 8; it++) {
            const int p = tid + it * 256;
            const int row = p >> 5, c16 = p & 31;
            CP_ASYNC16(sb + (dstw + row * stridew + c16 * 4) * 4,
                       src + row * 128 + c16 * 4);
        }
    };

    // group 0: Q + K0 + V0; group 1: K1 + V1 (prefetch)
    stage(SQ, 132, qbase + (size_t)q0 * 128);
    stage(SKB(0), 132, kbase);
    stage(SVB(0), 136, vbase);
    CP_COMMIT();
    if (qt > 0) {
        stage(SKB(1), 132, kbase + 64 * 128);
        stage(SVB(1), 136, vbase + 64 * 128);
        CP_COMMIT();
    }

    if (tid < 64) { sm[AMI + tid] = -1e30f; sm[ALI + tid] = 0.f; }

    float o[8][4];
#pragma unroll
    for (int i = 0; i < 8; i++)
#pragma unroll
        for (int q = 0; q < 4; q++) o[i][q] = 0.f;

    for (int kt = 0; kt <= qt; kt++) {
        const int buf = kt & 1;
        // wait for group kt (one newer group may stay in flight)
        if (kt < qt) { CP_WAIT1(); } else { CP_WAIT0(); }
        __syncthreads();

        // ---- S = Q K^T (single tf32, ldmatrix fragments) ----
        float sacc[4][4];
#pragma unroll
        for (int nf = 0; nf < 4; nf++)
#pragma unroll
            for (int q = 0; q < 4; q++) sacc[nf][q] = 0.f;

#pragma unroll
        for (int dc = 0; dc < 16; dc++) {
            const int d0 = dc * 8;
            uint32_t a[4];
            LDMX4(a, sb + (SQ + (arow + frow) * 132 + d0 + fcol) * 4);
#pragma unroll
            for (int nfp = 0; nfp < 2; nfp++) {
                uint32_t bf[4];
                const int krow = wn * 32 + nfp * 16 + brow;
                LDMX4(bf, sb + (SKB(buf) + krow * 132 + d0 + bcol) * 4);
#pragma unroll
                for (int i = 0; i < 2; i++) {
                    const int nf = nfp * 2 + i;
                    MMA_TF32(sacc[nf], a[0], a[1], a[2], a[3],
                             bf[i * 2], bf[i * 2 + 1]);
                }
            }
        }

        // ---- causal mask (diagonal tile only) ----
        if (kt == qt) {
            const int lrA = arow + g, lrB = lrA + 8;
#pragma unroll
            for (int nf = 0; nf < 4; nf++) {
                const int lc = wn * 32 + nf * 8 + 2 * tig;
                if (lc > lrA)     sacc[nf][0] = -1e30f;
                if (lc + 1 > lrA) sacc[nf][1] = -1e30f;
                if (lc > lrB)     sacc[nf][2] = -1e30f;
                if (lc + 1 > lrB) sacc[nf][3] = -1e30f;
            }
        }

        // ---- row max ----
        float mA = -1e30f, mB = -1e30f;
#pragma unroll
        for (int nf = 0; nf < 4; nf++) {
            mA = fmaxf(mA, fmaxf(sacc[nf][0], sacc[nf][1]));
            mB = fmaxf(mB, fmaxf(sacc[nf][2], sacc[nf][3]));
        }
        mA = fmaxf(mA, __shfl_xor_sync(0xffffffffu, mA, 1));
        mA = fmaxf(mA, __shfl_xor_sync(0xffffffffu, mA, 2));
        mB = fmaxf(mB, __shfl_xor_sync(0xffffffffu, mB, 1));
        mB = fmaxf(mB, __shfl_xor_sync(0xffffffffu, mB, 2));
        if (tig == 0) {
            sm[APMX + wn * 64 + arow + g] = mA;
            sm[APMX + wn * 64 + arow + g + 8] = mB;
        }
        __syncthreads();
        if (tid < 64) {
            const float mnew = fmaxf(sm[AMI + tid],
                                     fmaxf(sm[APMX + tid], sm[APMX + 64 + tid]));
            sm[AAL + tid] = __expf(sm[AMI + tid] - mnew);
            sm[AMI + tid] = mnew;
        }
        __syncthreads();

        // ---- p = exp(s - m), write P (rounded), row sums, rescale O ----
        const float mnA = sm[AMI + arow + g], mnB = sm[AMI + arow + g + 8];
        const float alA = sm[AAL + arow + g], alB = sm[AAL + arow + g + 8];
        float sumA = 0.f, sumB = 0.f;
#pragma unroll
        for (int nf = 0; nf < 4; nf++) {
            const float p0 = __expf(sacc[nf][0] - mnA);
            const float p1 = __expf(sacc[nf][1] - mnA);
            const float p2 = __expf(sacc[nf][2] - mnB);
            const float p3 = __expf(sacc[nf][3] - mnB);
            sumA += p0 + p1; sumB += p2 + p3;
            const int col = wn * 32 + nf * 8 + 2 * tig;
            *(float2*)&sm[SP + (arow + g) * 68 + col] = make_float2(rnaf(p0), rnaf(p1));
            *(float2*)&sm[SP + (arow + g + 8) * 68 + col] = make_float2(rnaf(p2), rnaf(p3));
        }
        sumA += __shfl_xor_sync(0xffffffffu, sumA, 1);
        sumA += __shfl_xor_sync(0xffffffffu, sumA, 2);
        sumB += __shfl_xor_sync(0xffffffffu, sumB, 1);
        sumB += __shfl_xor_sync(0xffffffffu, sumB, 2);
        if (tig == 0) {
            sm[APSM + wn * 64 + arow + g] = sumA;
            sm[APSM + wn * 64 + arow + g + 8] = sumB;
        }
#pragma unroll
        for (int nf2 = 0; nf2 < 8; nf2++) {
            o[nf2][0] *= alA; o[nf2][1] *= alA;
            o[nf2][2] *= alB; o[nf2][3] *= alB;
        }
        __syncthreads();
        if (tid < 64)
            sm[ALI + tid] = sm[ALI + tid] * sm[AAL + tid]
                          + sm[APSM + tid] + sm[APSM + 64 + tid];

        // ---- O += P @ V (tf32, P via ldmatrix, V scalar) ----
#pragma unroll
        for (int kc = 0; kc < 8; kc++) {
            uint32_t a[4];
            LDMX4(a, sb + (SP + (arow + frow) * 68 + kc * 8 + fcol) * 4);
#pragma unroll
            for (int nf2 = 0; nf2 < 8; nf2++) {
                const int d = wn * 64 + nf2 * 8 + g;
                const uint32_t b0 = U(sm[SVB(buf) + (kc * 8 + tig) * 136 + d]);
                const uint32_t b1 = U(sm[SVB(buf) + (kc * 8 + tig + 4) * 136 + d]);
                MMA_TF32(o[nf2], a[0], a[1], a[2], a[3], b0, b1);
            }
        }
        __syncthreads();   // all reads of buf done -> safe to refill it

        // prefetch group kt+2 into this iteration's buffer
        if (kt + 2 <= qt) {
            const int knext = (kt + 2) * 64;
            stage(SKB(buf), 132, kbase + (size_t)knext * 128);
            stage(SVB(buf), 136, vbase + (size_t)knext * 128);
            CP_COMMIT();
        }
    }

    // ---- epilogue: normalize, round to tf32 (feeds gemm2), write g_y ----
    const float invA = 1.f / sm[ALI + arow + g];
    const float invB = 1.f / sm[ALI + arow + g + 8];
    const int tA = q0 + arow + g, tB = tA + 8;
#pragma unroll
    for (int nf2 = 0; nf2 < 8; nf2++) {
        const int d = wn * 64 + nf2 * 8 + 2 * tig;
        *(float2*)(g_y + ((size_t)bb * 512 + tA) * 2048 + hh * 128 + d) =
            make_float2(rnaf(o[nf2][0] * invA), rnaf(o[nf2][1] * invA));
        *(float2*)(g_y + ((size_t)bb * 512 + tB) * 2048 + hh * 128 + d) =
            make_float2(rnaf(o[nf2][2] * invB), rnaf(o[nf2][3] * invB));
    }
}

// ---------------------------------------------------------------------------
extern "C" void kernel_launch(void* const* d_in, const int* in_sizes, int n_in,
                              void* d_out, int out_size)
{
    (void)in_sizes; (void)n_in; (void)out_size;
    const float* x     = (const float*)d_in[0];
    const float* w_qkv = (const float*)d_in[1];
    const float* w_out = (const float*)d_in[2];
    float* out = (float*)d_out;

    float *y_ptr, *xr_ptr, *wqr_ptr, *wor_ptr;
    cudaGetSymbolAddress((void**)&y_ptr, g_y);
    cudaGetSymbolAddress((void**)&xr_ptr, g_xr);
    cudaGetSymbolAddress((void**)&wqr_ptr, g_wqr);
    cudaGetSymbolAddress((void**)&wor_ptr, g_wor);

    cudaFuncSetAttribute(gemm_mma<1>, cudaFuncAttributeMaxDynamicSharedMemorySize, GEMM_SMEM_BYTES);
    cudaFuncSetAttribute(gemm_mma<0>, cudaFuncAttributeMaxDynamicSharedMemorySize, GEMM_SMEM_BYTES);
    cudaFuncSetAttribute(attn_mma, cudaFuncAttributeMaxDynamicSharedMemorySize, ATTN2_SMEM_BYTES);

    // 0) pre-round inputs + rope tables
    round_tf32<<<(8388608 + 255) / 256, 256>>>(x, xr_ptr, 8388608);
    round_tf32<<<(3145728 + 255) / 256, 256>>>(w_qkv, wqr_ptr, 3145728);
    round_tf32<<<(1048576 + 255) / 256, 256>>>(w_out, wor_ptr, 1048576);
    build_tables<<<64, 256>>>();

    // 1) QKV projection (scatter to q/k/v; v rounded)
    {
        dim3 grid(6144 / 128, 16384 / 128);
        gemm_mma<1><<<grid, 256, GEMM_SMEM_BYTES>>>(xr_ptr, wqr_ptr, nullptr, 16384, 6144, 2048);
    }
    // 1.5) in-place rope + scale + tf32-round of q, k
    {
        dim3 grid(128, 512, 2);
        rope_round<<<grid, 256>>>();
    }
    // 2) Attention (pure cp.async staging, double-buffered K/V)
    {
        dim3 grid(8, 16, 32);
        attn_mma<<<grid, 256, ATTN2_SMEM_BYTES>>>();
    }
    // 3) Output projection
    {
        dim3 grid(2048 / 128, 16384 / 128);
        gemm_mma<0><<<grid, 256, GEMM_SMEM_BYTES>>>(y_ptr, wor_ptr, out, 16384, 2048, 2048);
    }
}

// round 10
// speedup vs baseline: 1.8009x; 1.6355x over previous
#include <cuda_runtime.h>
#include <cuda_fp16.h>
#include <math.h>
#include <cstdint>

// Shapes: x[32,512,2048] f32, w_qkv[6144,2048], w_out[2048,2048], out[32,512,2048]

// Scratch (device globals: allocation-free per harness rules)
__device__ float  g_q[32L * 16 * 512 * 128];    // [B,H,T,D] fp32 pre-rope
__device__ float  g_k[32L * 16 * 512 * 128];
__device__ __half g_qh[32L * 16 * 512 * 128];   // roped+scaled, fp16
__device__ __half g_kh[32L * 16 * 512 * 128];   // roped, fp16
__device__ __half g_vh[32L * 16 * 512 * 128];   // fp16 (gemm1 epilogue)
__device__ __half g_yh[32L * 512 * 2048];       // [B,T,C] attn out fp16
__device__ __half g_xh[32L * 512 * 2048];       // x fp16
__device__ __half g_wqh[6144L * 2048];          // w_qkv fp16
__device__ __half g_woh[2048L * 2048];          // w_out fp16
__device__ float  g_cos[512 * 32];
__device__ float  g_sin[512 * 32];

// ===========================================================================
// Helpers
// ===========================================================================
__device__ __forceinline__ uint32_t smem_u32(const void* p) {
    uint32_t a;
    asm("{ .reg .u64 t; cvta.to.shared.u64 t, %1; cvt.u32.u64 %0, t; }" : "=r"(a) : "l"(p));
    return a;
}
__device__ __forceinline__ uint32_t swz(uint32_t off) { return off ^ ((off >> 3) & 0x70); }

#define CP_ASYNC16(dst, src) \
    asm volatile("cp.async.cg.shared.global [%0], [%1], 16;" :: "r"(dst), "l"(src))
#define CP_COMMIT() asm volatile("cp.async.commit_group;" ::: "memory")
#define CP_WAIT1() asm volatile("cp.async.wait_group 1;" ::: "memory")
#define CP_WAIT0() asm volatile("cp.async.wait_group 0;" ::: "memory")

#define MMA_F16(c, A0, A1, A2, A3, B0, B1) \
    asm volatile("mma.sync.aligned.m16n8k16.row.col.f32.f16.f16.f32 " \
        "{%0,%1,%2,%3},{%4,%5,%6,%7},{%8,%9},{%0,%1,%2,%3};" \
        : "+f"((c)[0]), "+f"((c)[1]), "+f"((c)[2]), "+f"((c)[3]) \
        : "r"(A0), "r"(A1), "r"(A2), "r"(A3), "r"(B0), "r"(B1))

#define LDMX4(r, addr) \
    asm volatile("ldmatrix.sync.aligned.m8n8.x4.shared.b16 {%0,%1,%2,%3}, [%4];" \
        : "=r"((r)[0]), "=r"((r)[1]), "=r"((r)[2]), "=r"((r)[3]) : "r"(addr))
#define LDMX4T(r, addr) \
    asm volatile("ldmatrix.sync.aligned.m8n8.x4.trans.shared.b16 {%0,%1,%2,%3}, [%4];" \
        : "=r"((r)[0]), "=r"((r)[1]), "=r"((r)[2]), "=r"((r)[3]) : "r"(addr))

// ===========================================================================
// f32 -> f16 conversion pass
// ===========================================================================
__global__ void to_half(const float* __restrict__ in, __half* __restrict__ out, int n4)
{
    int i = blockIdx.x * blockDim.x + threadIdx.x;
    if (i >= n4) return;
    float4 v = ((const float4*)in)[i];
    ((__half2*)out)[i * 2]     = __floats2half2_rn(v.x, v.y);
    ((__half2*)out)[i * 2 + 1] = __floats2half2_rn(v.z, v.w);
}

// rope tables (double-precision build, matches numpy float64 path)
__global__ void build_tables()
{
    int i = blockIdx.x * blockDim.x + threadIdx.x;
    if (i >= 512 * 32) return;
    int t = i >> 5, j = i & 31;
    double freq = pow(10000.0, -(double)j / 32.0);
    double ang = (double)t * freq;
    g_cos[i] = (float)cos(ang);
    g_sin[i] = (float)sin(ang);
}

// ===========================================================================
// rope (fp32) + scale + fp16 convert: g_q -> g_qh (scaled), g_k -> g_kh.
// Block 256 = 4 rows. Grid (128 t-groups, 512 bh, 2 sel).
// ===========================================================================
__global__ void __launch_bounds__(256) rope_round()
{
    const int tid = threadIdx.x;
    const int s = tid & 63;
    const int t = blockIdx.x * 4 + (tid >> 6);
    const int bh = blockIdx.y;
    const int sel = blockIdx.z;
    const size_t off = ((size_t)bh * 512 + t) * 128;
    const float* p = (sel ? g_k : g_q) + off;
    __half* ph = (sel ? g_kh : g_qh) + off;
    const float scale = sel ? 1.0f : 0.08838834764831845f;

    if (s < 32) {
        const float c = g_cos[t * 32 + s], si = g_sin[t * 32 + s];
        const float x1 = p[s], x2 = p[s + 32];
        ph[s]      = __float2half_rn((x1 * c - x2 * si) * scale);
        ph[s + 32] = __float2half_rn((x2 * c + x1 * si) * scale);
    } else {
        const int d1 = s + 32, d2 = s + 64;
        ph[d1] = __float2half_rn(p[d1] * scale);
        ph[d2] = __float2half_rn(p[d2] * scale);
    }
}

// ===========================================================================
// fp16 mma.sync GEMM: C[m,n] = sum_k A[m,k]*B[n,k], fp32 accumulate.
// 128x128 tile, BK=64 halfs (128B rows, same swizzle geometry as before),
// 8 warps (2x4), warp 64x32, 2-stage cp.async, 2 CTA/SM.
// MODE 0: fp32 row-major store. MODE 1: scatter q/k fp32 + v fp16 [B,H,T,D].
// ===========================================================================
#define GEMM_SMEM_BYTES 65536   // 2 bufs x (16KB A + 16KB B)

template <int MODE>
__global__ void __launch_bounds__(256, 2) gemm_h(
    const __half* __restrict__ A, const __half* __restrict__ Bm,
    float* __restrict__ Cout, int M, int N, int K)
{
    extern __shared__ char smraw[];
    const uint32_t sb = smem_u32(smraw);
    const int tid = threadIdx.x;
    const int warp = tid >> 5, lane = tid & 31;
    const int wm = warp >> 2, wn = warp & 3;
    const int m0 = blockIdx.y * 128, n0 = blockIdx.x * 128;
    const int lrow = lane & 15, lcol = (lane >> 4) * 16;

    float acc[4][4][4];
#pragma unroll
    for (int i = 0; i < 4; i++)
#pragma unroll
        for (int j = 0; j < 4; j++)
#pragma unroll
            for (int q = 0; q < 4; q++) acc[i][j][q] = 0.f;

    const int nch = K / 64;   // 32

    auto load_chunk = [&](int c, int buf) {
        const int k0 = c * 64;
        const uint32_t abase = sb + buf * 32768;
        const uint32_t bbase = abase + 16384;
#pragma unroll
        for (int it = 0; it < 4; it++) {
            const int t = tid + it * 256;
            const int row = t >> 3, ch = t & 7;
            CP_ASYNC16(abase + swz((uint32_t)(row * 128 + ch * 16)),
                       A + (size_t)(m0 + row) * K + k0 + ch * 8);
        }
#pragma unroll
        for (int it = 0; it < 4; it++) {
            const int t = tid + it * 256;
            const int row = t >> 3, ch = t & 7;
            CP_ASYNC16(bbase + swz((uint32_t)(row * 128 + ch * 16)),
                       Bm + (size_t)(n0 + row) * K + k0 + ch * 8);
        }
    };

    load_chunk(0, 0);
    CP_COMMIT();

    for (int c = 0; c < nch; c++) {
        const int buf = c & 1;
        const bool has_next = (c + 1 < nch);
        if (has_next) {
            load_chunk(c + 1, (c + 1) & 1);
            CP_COMMIT();
            CP_WAIT1();
        } else {
            CP_WAIT0();
        }
        __syncthreads();

        const uint32_t abase = sb + buf * 32768;
        const uint32_t bbase = abase + 16384;

#pragma unroll
        for (int ks = 0; ks < 4; ks++) {   // k16 steps within BK=64
            uint32_t a[4][4], b[2][4];
#pragma unroll
            for (int mf = 0; mf < 4; mf++) {
                const int row = wm * 64 + mf * 16 + lrow;
                LDMX4(a[mf], abase + swz((uint32_t)(row * 128 + ks * 32 + lcol)));
            }
#pragma unroll
            for (int nb = 0; nb < 2; nb++) {
                const int row = wn * 32 + nb * 16 + lrow;
                LDMX4(b[nb], bbase + swz((uint32_t)(row * 128 + ks * 32 + lcol)));
            }
#pragma unroll
            for (int mf = 0; mf < 4; mf++)
#pragma unroll
                for (int nf = 0; nf < 4; nf++) {
                    const int nb = nf >> 1, i = nf & 1;
                    MMA_F16(acc[mf][nf], a[mf][0], a[mf][1], a[mf][2], a[mf][3],
                            b[nb][i], b[nb][i + 2]);
                }
        }
        __syncthreads();
    }

    // epilogue (C fragment layout identical to m16n8k8)
    const int g = lane >> 2, tig = lane & 3;
    if (MODE == 0) {
#pragma unroll
        for (int mf = 0; mf < 4; mf++) {
            const int mA = m0 + wm * 64 + mf * 16 + g;
#pragma unroll
            for (int nf = 0; nf < 4; nf++) {
                const int nn = n0 + wn * 32 + nf * 8 + tig * 2;
                *(float2*)(Cout + (size_t)mA * N + nn) =
                    make_float2(acc[mf][nf][0], acc[mf][nf][1]);
                *(float2*)(Cout + (size_t)(mA + 8) * N + nn) =
                    make_float2(acc[mf][nf][2], acc[mf][nf][3]);
            }
        }
    } else {
        const int which = n0 >> 11;
        const int h = (n0 & 2047) >> 7;
#pragma unroll
        for (int mf = 0; mf < 4; mf++) {
            const int mA = m0 + wm * 64 + mf * 16 + g;
            const int bA = mA >> 9, tA = mA & 511;
            const int mB = mA + 8;
            const int bB = mB >> 9, tB = mB & 511;
#pragma unroll
            for (int nf = 0; nf < 4; nf++) {
                const int d = wn * 32 + nf * 8 + tig * 2;
                const size_t iA = ((size_t)(bA * 16 + h) * 512 + tA) * 128 + d;
                const size_t iB = ((size_t)(bB * 16 + h) * 512 + tB) * 128 + d;
                if (which == 2) {
                    *(__half2*)&g_vh[iA] = __floats2half2_rn(acc[mf][nf][0], acc[mf][nf][1]);
                    *(__half2*)&g_vh[iB] = __floats2half2_rn(acc[mf][nf][2], acc[mf][nf][3]);
                } else {
                    float* basep = (which == 0) ? g_q : g_k;
                    *(float2*)(basep + iA) = make_float2(acc[mf][nf][0], acc[mf][nf][1]);
                    *(float2*)(basep + iB) = make_float2(acc[mf][nf][2], acc[mf][nf][3]);
                }
            }
        }
    }
}

// ===========================================================================
// fp16 tensor-core flash attention. Block = (64 q-rows, one (b,h)).
// 8 warps: wm 0..3 (16 q-rows), wn 0..1 (key/d half).
// QK^T + PV in fp16 mma (fp32 accum). Double-buffered K/V cp.async.
// Tiles: half rows of 128 halfs, stride 136 halfs (272B; 17 chunks, conflict-free).
// ===========================================================================
// byte offsets
#define SQB   0                       // 64 x 272B
#define SKBb(b) (17408 + (b) * 17408)
#define SVBb(b) (52224 + (b) * 17408)
#define SPB   87040                   // 64 x 144B
#define FSMB  96256                   // fp32 stats
// float indices within fsm
#define AMI 0
#define ALI 64
#define AAL 128
#define APMX 192                      // [2][64]
#define APSM 320                      // [2][64]
#define ATTN2_SMEM_BYTES (96256 + 448 * 4)

__global__ void __launch_bounds__(256, 1) attn_mma()
{
    extern __shared__ char smc[];
    const uint32_t sb = smem_u32(smc);
    float* fsm = (float*)(smc + FSMB);
    const int tid = threadIdx.x;
    const int warp = tid >> 5, lane = tid & 31;
    const int wm = warp >> 1, wn = warp & 1;
    const int g = lane >> 2, tig = lane & 3;
    const int lrow = lane & 15, lcol = (lane >> 4) * 16;
    const int qt = blockIdx.x, hh = blockIdx.y, bb = blockIdx.z;
    const int bh = bb * 16 + hh, q0 = qt * 64;
    const int arow = wm * 16;

    const __half* qbase = g_qh + (size_t)bh * 512 * 128;
    const __half* kbase = g_kh + (size_t)bh * 512 * 128;
    const __half* vbase = g_vh + (size_t)bh * 512 * 128;

    // cp.async 64x128-half tile into padded smem (row stride 272B)
    auto stage = [&](uint32_t dstB, const __half* src) {
#pragma unroll
        for (int it = 0; it < 4; it++) {
            const int p = tid + it * 256;
            const int row = p >> 4, ch = p & 15;
            CP_ASYNC16(sb + dstB + row * 272 + ch * 16,
                       src + row * 128 + ch * 8);
        }
    };

    stage(SQB, qbase + (size_t)q0 * 128);
    stage(SKBb(0), kbase);
    stage(SVBb(0), vbase);
    CP_COMMIT();
    if (qt > 0) {
        stage(SKBb(1), kbase + 64 * 128);
        stage(SVBb(1), vbase + 64 * 128);
        CP_COMMIT();
    }

    if (tid < 64) { fsm[AMI + tid] = -1e30f; fsm[ALI + tid] = 0.f; }

    float o[8][4];
#pragma unroll
    for (int i = 0; i < 8; i++)
#pragma unroll
        for (int q = 0; q < 4; q++) o[i][q] = 0.f;

    for (int kt = 0; kt <= qt; kt++) {
        const int buf = kt & 1;
        if (kt < qt) { CP_WAIT1(); } else { CP_WAIT0(); }
        __syncthreads();

        // ---- S = Q K^T (fp16 mma) ----
        float sacc[4][4];
#pragma unroll
        for (int nf = 0; nf < 4; nf++)
#pragma unroll
            for (int q = 0; q < 4; q++) sacc[nf][q] = 0.f;

#pragma unroll
        for (int dc = 0; dc < 8; dc++) {   // k16 steps over D=128
            uint32_t a[4];
            LDMX4(a, sb + SQB + (uint32_t)((arow + lrow) * 272 + dc * 32 + lcol));
#pragma unroll
            for (int nb = 0; nb < 2; nb++) {
                uint32_t bf[4];
                LDMX4(bf, sb + SKBb(buf) +
                          (uint32_t)((wn * 32 + nb * 16 + lrow) * 272 + dc * 32 + lcol));
#pragma unroll
                for (int i = 0; i < 2; i++) {
                    const int nf = nb * 2 + i;
                    MMA_F16(sacc[nf], a[0], a[1], a[2], a[3], bf[i], bf[i + 2]);
                }
            }
        }

        // ---- causal mask (diagonal tile only) ----
        if (kt == qt) {
            const int lrA = arow + g, lrB = lrA + 8;
#pragma unroll
            for (int nf = 0; nf < 4; nf++) {
                const int lc = wn * 32 + nf * 8 + 2 * tig;
                if (lc > lrA)     sacc[nf][0] = -1e30f;
                if (lc + 1 > lrA) sacc[nf][1] = -1e30f;
                if (lc > lrB)     sacc[nf][2] = -1e30f;
                if (lc + 1 > lrB) sacc[nf][3] = -1e30f;
            }
        }

        // ---- row max ----
        float mA = -1e30f, mB = -1e30f;
#pragma unroll
        for (int nf = 0; nf < 4; nf++) {
            mA = fmaxf(mA, fmaxf(sacc[nf][0], sacc[nf][1]));
            mB = fmaxf(mB, fmaxf(sacc[nf][2], sacc[nf][3]));
        }
        mA = fmaxf(mA, __shfl_xor_sync(0xffffffffu, mA, 1));
        mA = fmaxf(mA, __shfl_xor_sync(0xffffffffu, mA, 2));
        mB = fmaxf(mB, __shfl_xor_sync(0xffffffffu, mB, 1));
        mB = fmaxf(mB, __shfl_xor_sync(0xffffffffu, mB, 2));
        if (tig == 0) {
            fsm[APMX + wn * 64 + arow + g] = mA;
            fsm[APMX + wn * 64 + arow + g + 8] = mB;
        }
        __syncthreads();
        if (tid < 64) {
            const float mnew = fmaxf(fsm[AMI + tid],
                                     fmaxf(fsm[APMX + tid], fsm[APMX + 64 + tid]));
            fsm[AAL + tid] = __expf(fsm[AMI + tid] - mnew);
            fsm[AMI + tid] = mnew;
        }
        __syncthreads();

        // ---- p = exp(s - m), write P (fp16), row sums, rescale O ----
        const float mnA = fsm[AMI + arow + g], mnB = fsm[AMI + arow + g + 8];
        const float alA = fsm[AAL + arow + g], alB = fsm[AAL + arow + g + 8];
        float sumA = 0.f, sumB = 0.f;
#pragma unroll
        for (int nf = 0; nf < 4; nf++) {
            const float p0 = __expf(sacc[nf][0] - mnA);
            const float p1 = __expf(sacc[nf][1] - mnA);
            const float p2 = __expf(sacc[nf][2] - mnB);
            const float p3 = __expf(sacc[nf][3] - mnB);
            sumA += p0 + p1; sumB += p2 + p3;
            const int col = wn * 32 + nf * 8 + 2 * tig;
            *(__half2*)(smc + SPB + ((arow + g) * 72 + col) * 2) =
                __floats2half2_rn(p0, p1);
            *(__half2*)(smc + SPB + ((arow + g + 8) * 72 + col) * 2) =
                __floats2half2_rn(p2, p3);
        }
        sumA += __shfl_xor_sync(0xffffffffu, sumA, 1);
        sumA += __shfl_xor_sync(0xffffffffu, sumA, 2);
        sumB += __shfl_xor_sync(0xffffffffu, sumB, 1);
        sumB += __shfl_xor_sync(0xffffffffu, sumB, 2);
        if (tig == 0) {
            fsm[APSM + wn * 64 + arow + g] = sumA;
            fsm[APSM + wn * 64 + arow + g + 8] = sumB;
        }
#pragma unroll
        for (int nf2 = 0; nf2 < 8; nf2++) {
            o[nf2][0] *= alA; o[nf2][1] *= alA;
            o[nf2][2] *= alB; o[nf2][3] *= alB;
        }
        __syncthreads();
        if (tid < 64)
            fsm[ALI + tid] = fsm[ALI + tid] * fsm[AAL + tid]
                           + fsm[APSM + tid] + fsm[APSM + 64 + tid];

        // ---- O += P @ V (fp16 mma, V via ldmatrix.trans) ----
#pragma unroll
        for (int kc = 0; kc < 4; kc++) {   // k16 steps over 64 keys
            uint32_t a[4];
            LDMX4(a, sb + SPB + (uint32_t)((arow + lrow) * 144 + kc * 32 + lcol));
#pragma unroll
            for (int dblk = 0; dblk < 4; dblk++) {   // 16 d per block
                uint32_t bf[4];
                LDMX4T(bf, sb + SVBb(buf) +
                           (uint32_t)((kc * 16 + lrow) * 272 + wn * 128 + dblk * 32 + lcol));
                MMA_F16(o[dblk * 2],     a[0], a[1], a[2], a[3], bf[0], bf[1]);
                MMA_F16(o[dblk * 2 + 1], a[0], a[1], a[2], a[3], bf[2], bf[3]);
            }
        }
        __syncthreads();   // all reads of buf done -> safe to refill

        if (kt + 2 <= qt) {
            const int knext = (kt + 2) * 64;
            stage(SKBb(buf), kbase + (size_t)knext * 128);
            stage(SVBb(buf), vbase + (size_t)knext * 128);
            CP_COMMIT();
        }
    }

    // ---- epilogue: normalize, convert fp16, write g_yh ----
    const float invA = 1.f / fsm[ALI + arow + g];
    const float invB = 1.f / fsm[ALI + arow + g + 8];
    const int tA = q0 + arow + g, tB = tA + 8;
#pragma unroll
    for (int nf2 = 0; nf2 < 8; nf2++) {
        const int d = wn * 64 + nf2 * 8 + 2 * tig;
        *(__half2*)&g_yh[((size_t)bb * 512 + tA) * 2048 + hh * 128 + d] =
            __floats2half2_rn(o[nf2][0] * invA, o[nf2][1] * invA);
        *(__half2*)&g_yh[((size_t)bb * 512 + tB) * 2048 + hh * 128 + d] =
            __floats2half2_rn(o[nf2][2] * invB, o[nf2][3] * invB);
    }
}

// ---------------------------------------------------------------------------
extern "C" void kernel_launch(void* const* d_in, const int* in_sizes, int n_in,
                              void* d_out, int out_size)
{
    (void)in_sizes; (void)n_in; (void)out_size;
    const float* x     = (const float*)d_in[0];
    const float* w_qkv = (const float*)d_in[1];
    const float* w_out = (const float*)d_in[2];
    float* out = (float*)d_out;

    __half *xh_ptr, *wqh_ptr, *woh_ptr, *yh_ptr;
    cudaGetSymbolAddress((void**)&xh_ptr,  g_xh);
    cudaGetSymbolAddress((void**)&wqh_ptr, g_wqh);
    cudaGetSymbolAddress((void**)&woh_ptr, g_woh);
    cudaGetSymbolAddress((void**)&yh_ptr,  g_yh);

    cudaFuncSetAttribute(gemm_h<1>, cudaFuncAttributeMaxDynamicSharedMemorySize, GEMM_SMEM_BYTES);
    cudaFuncSetAttribute(gemm_h<0>, cudaFuncAttributeMaxDynamicSharedMemorySize, GEMM_SMEM_BYTES);
    cudaFuncSetAttribute(attn_mma, cudaFuncAttributeMaxDynamicSharedMemorySize, ATTN2_SMEM_BYTES);

    // 0) convert inputs to fp16 + rope tables
    to_half<<<(8388608 + 255) / 256, 256>>>(x, xh_ptr, 8388608);
    to_half<<<(3145728 + 255) / 256, 256>>>(w_qkv, wqh_ptr, 3145728);
    to_half<<<(1048576 + 255) / 256, 256>>>(w_out, woh_ptr, 1048576);
    build_tables<<<64, 256>>>();

    // 1) QKV projection (fp16 mma; q/k fp32, v fp16 scatter)
    {
        dim3 grid(6144 / 128, 16384 / 128);
        gemm_h<1><<<grid, 256, GEMM_SMEM_BYTES>>>(xh_ptr, wqh_ptr, nullptr, 16384, 6144, 2048);
    }
    // 1.5) rope + scale + fp16 convert of q, k
    {
        dim3 grid(128, 512, 2);
        rope_round<<<grid, 256>>>();
    }
    // 2) Attention (fp16 tensor-core flash)
    {
        dim3 grid(8, 16, 32);
        attn_mma<<<grid, 256, ATTN2_SMEM_BYTES>>>();
    }
    // 3) Output projection (fp16 mma, fp32 out)
    {
        dim3 grid(2048 / 128, 16384 / 128);
        gemm_h<0><<<grid, 256, GEMM_SMEM_BYTES>>>(yh_ptr, woh_ptr, out, 16384, 2048, 2048);
    }
}

// round 12
// speedup vs baseline: 1.8907x; 1.0498x over previous
#include <cuda_runtime.h>
#include <cuda_fp16.h>
#include <math.h>
#include <cstdint>

// Shapes: x[32,512,2048] f32, w_qkv[6144,2048], w_out[2048,2048], out[32,512,2048]

// Scratch (device globals: allocation-free per harness rules)
__device__ __half g_qh[32L * 16 * 512 * 128];   // [B,H,T,D] fp16; rope applied in-place
__device__ __half g_kh[32L * 16 * 512 * 128];
__device__ __half g_vh[32L * 16 * 512 * 128];
__device__ __half g_yh[32L * 512 * 2048];       // [B,T,C] attn out fp16
__device__ __half g_xh[32L * 512 * 2048];       // x fp16
__device__ __half g_wqh[6144L * 2048];          // w_qkv fp16
__device__ __half g_woh[2048L * 2048];          // w_out fp16
__device__ float  g_cos[512 * 32];
__device__ float  g_sin[512 * 32];

// ===========================================================================
// Helpers
// ===========================================================================
__device__ __forceinline__ uint32_t smem_u32(const void* p) {
    uint32_t a;
    asm("{ .reg .u64 t; cvta.to.shared.u64 t, %1; cvt.u32.u64 %0, t; }" : "=r"(a) : "l"(p));
    return a;
}
__device__ __forceinline__ uint32_t swz(uint32_t off) { return off ^ ((off >> 3) & 0x70); }

#define CP_ASYNC16(dst, src) \
    asm volatile("cp.async.cg.shared.global [%0], [%1], 16;" :: "r"(dst), "l"(src))
#define CP_COMMIT() asm volatile("cp.async.commit_group;" ::: "memory")
#define CP_WAIT1() asm volatile("cp.async.wait_group 1;" ::: "memory")
#define CP_WAIT0() asm volatile("cp.async.wait_group 0;" ::: "memory")

#define MMA_F16(c, A0, A1, A2, A3, B0, B1) \
    asm volatile("mma.sync.aligned.m16n8k16.row.col.f32.f16.f16.f32 " \
        "{%0,%1,%2,%3},{%4,%5,%6,%7},{%8,%9},{%0,%1,%2,%3};" \
        : "+f"((c)[0]), "+f"((c)[1]), "+f"((c)[2]), "+f"((c)[3]) \
        : "r"(A0), "r"(A1), "r"(A2), "r"(A3), "r"(B0), "r"(B1))

#define LDMX4(r, addr) \
    asm volatile("ldmatrix.sync.aligned.m8n8.x4.shared.b16 {%0,%1,%2,%3}, [%4];" \
        : "=r"((r)[0]), "=r"((r)[1]), "=r"((r)[2]), "=r"((r)[3]) : "r"(addr))
#define LDMX4T(r, addr) \
    asm volatile("ldmatrix.sync.aligned.m8n8.x4.trans.shared.b16 {%0,%1,%2,%3}, [%4];" \
        : "=r"((r)[0]), "=r"((r)[1]), "=r"((r)[2]), "=r"((r)[3]) : "r"(addr))

// ===========================================================================
// f32 -> f16 conversion pass
// ===========================================================================
__global__ void to_half(const float* __restrict__ in, __half* __restrict__ out, int n4)
{
    int i = blockIdx.x * blockDim.x + threadIdx.x;
    if (i >= n4) return;
    float4 v = ((const float4*)in)[i];
    ((__half2*)out)[i * 2]     = __floats2half2_rn(v.x, v.y);
    ((__half2*)out)[i * 2 + 1] = __floats2half2_rn(v.z, v.w);
}

// rope tables (double-precision build, matches numpy float64 path)
__global__ void build_tables()
{
    int i = blockIdx.x * blockDim.x + threadIdx.x;
    if (i >= 512 * 32) return;
    int t = i >> 5, j = i & 31;
    double freq = pow(10000.0, -(double)j / 32.0);
    double ang = (double)t * freq;
    g_cos[i] = (float)cos(ang);
    g_sin[i] = (float)sin(ang);
}

// ===========================================================================
// In-place rope on fp16 q (plus 1/sqrt(D) scale) and k.
// Block 256 = 4 rows x 64 thr. Grid (128 t-groups, 512 bh, 2 sel).
// Each thread exclusively owns its elements. k pass-dims untouched.
// ===========================================================================
__global__ void __launch_bounds__(256) rope_round()
{
    const int tid = threadIdx.x;
    const int s = tid & 63;
    const int t = blockIdx.x * 4 + (tid >> 6);
    const int bh = blockIdx.y;
    const int sel = blockIdx.z;
    __half* p = (sel ? g_kh : g_qh) + ((size_t)bh * 512 + t) * 128;
    const float scale = sel ? 1.0f : 0.08838834764831845f;

    if (s < 32) {
        const float c = g_cos[t * 32 + s], si = g_sin[t * 32 + s];
        const float x1 = __half2float(p[s]), x2 = __half2float(p[s + 32]);
        p[s]      = __float2half_rn((x1 * c - x2 * si) * scale);
        p[s + 32] = __float2half_rn((x2 * c + x1 * si) * scale);
    } else if (sel == 0) {
        const int d1 = s + 32, d2 = s + 64;
        p[d1] = __float2half_rn(__half2float(p[d1]) * scale);
        p[d2] = __float2half_rn(__half2float(p[d2]) * scale);
    }
}

// ===========================================================================
// fp16 mma.sync GEMM: C[m,n] = sum_k A[m,k]*B[n,k], fp32 accumulate.
// 128x128 tile, BK=64 halfs, 8 warps (2x4), warp 64x32, 2-stage cp.async, 2 CTA/SM.
// MODE 0: fp32 row-major store. MODE 1: scatter q/k/v fp16 [B,H,T,D].
// ===========================================================================
#define GEMM_SMEM_BYTES 65536

template <int MODE>
__global__ void __launch_bounds__(256, 2) gemm_h(
    const __half* __restrict__ A, const __half* __restrict__ Bm,
    float* __restrict__ Cout, int M, int N, int K)
{
    extern __shared__ char smraw[];
    const uint32_t sb = smem_u32(smraw);
    const int tid = threadIdx.x;
    const int warp = tid >> 5, lane = tid & 31;
    const int wm = warp >> 2, wn = warp & 3;
    const int m0 = blockIdx.y * 128, n0 = blockIdx.x * 128;
    const int lrow = lane & 15, lcol = (lane >> 4) * 16;

    float acc[4][4][4];
#pragma unroll
    for (int i = 0; i < 4; i++)
#pragma unroll
        for (int j = 0; j < 4; j++)
#pragma unroll
            for (int q = 0; q < 4; q++) acc[i][j][q] = 0.f;

    const int nch = K / 64;

    auto load_chunk = [&](int c, int buf) {
        const int k0 = c * 64;
        const uint32_t abase = sb + buf * 32768;
        const uint32_t bbase = abase + 16384;
#pragma unroll
        for (int it = 0; it < 4; it++) {
            const int t = tid + it * 256;
            const int row = t >> 3, ch = t & 7;
            CP_ASYNC16(abase + swz((uint32_t)(row * 128 + ch * 16)),
                       A + (size_t)(m0 + row) * K + k0 + ch * 8);
        }
#pragma unroll
        for (int it = 0; it < 4; it++) {
            const int t = tid + it * 256;
            const int row = t >> 3, ch = t & 7;
            CP_ASYNC16(bbase + swz((uint32_t)(row * 128 + ch * 16)),
                       Bm + (size_t)(n0 + row) * K + k0 + ch * 8);
        }
    };

    load_chunk(0, 0);
    CP_COMMIT();

    for (int c = 0; c < nch; c++) {
        const int buf = c & 1;
        const bool has_next = (c + 1 < nch);
        if (has_next) {
            load_chunk(c + 1, (c + 1) & 1);
            CP_COMMIT();
            CP_WAIT1();
        } else {
            CP_WAIT0();
        }
        __syncthreads();

        const uint32_t abase = sb + buf * 32768;
        const uint32_t bbase = abase + 16384;

#pragma unroll
        for (int ks = 0; ks < 4; ks++) {
            uint32_t a[4][4], b[2][4];
#pragma unroll
            for (int mf = 0; mf < 4; mf++) {
                const int row = wm * 64 + mf * 16 + lrow;
                LDMX4(a[mf], abase + swz((uint32_t)(row * 128 + ks * 32 + lcol)));
            }
#pragma unroll
            for (int nb = 0; nb < 2; nb++) {
                const int row = wn * 32 + nb * 16 + lrow;
                LDMX4(b[nb], bbase + swz((uint32_t)(row * 128 + ks * 32 + lcol)));
            }
#pragma unroll
            for (int mf = 0; mf < 4; mf++)
#pragma unroll
                for (int nf = 0; nf < 4; nf++) {
                    const int nb = nf >> 1, i = nf & 1;
                    MMA_F16(acc[mf][nf], a[mf][0], a[mf][1], a[mf][2], a[mf][3],
                            b[nb][i], b[nb][i + 2]);
                }
        }
        __syncthreads();
    }

    const int g = lane >> 2, tig = lane & 3;
    if (MODE == 0) {
#pragma unroll
        for (int mf = 0; mf < 4; mf++) {
            const int mA = m0 + wm * 64 + mf * 16 + g;
#pragma unroll
            for (int nf = 0; nf < 4; nf++) {
                const int nn = n0 + wn * 32 + nf * 8 + tig * 2;
                *(float2*)(Cout + (size_t)mA * N + nn) =
                    make_float2(acc[mf][nf][0], acc[mf][nf][1]);
                *(float2*)(Cout + (size_t)(mA + 8) * N + nn) =
                    make_float2(acc[mf][nf][2], acc[mf][nf][3]);
            }
        }
    } else {
        const int which = n0 >> 11;
        const int h = (n0 & 2047) >> 7;
        __half* basep = (which == 0) ? g_qh : (which == 1) ? g_kh : g_vh;
#pragma unroll
        for (int mf = 0; mf < 4; mf++) {
            const int mA = m0 + wm * 64 + mf * 16 + g;
            const int bA = mA >> 9, tA = mA & 511;
            const int mB = mA + 8;
            const int bB = mB >> 9, tB = mB & 511;
#pragma unroll
            for (int nf = 0; nf < 4; nf++) {
                const int d = wn * 32 + nf * 8 + tig * 2;
                const size_t iA = ((size_t)(bA * 16 + h) * 512 + tA) * 128 + d;
                const size_t iB = ((size_t)(bB * 16 + h) * 512 + tB) * 128 + d;
                *(__half2*)&basep[iA] = __floats2half2_rn(acc[mf][nf][0], acc[mf][nf][1]);
                *(__half2*)&basep[iB] = __floats2half2_rn(acc[mf][nf][2], acc[mf][nf][3]);
            }
        }
    }
}

// ===========================================================================
// fp16 tensor-core flash attention, Tq = 128 q-rows per CTA.
// 8 warps: wm 0..3 (32 q-rows via rg 0..1), wn 0..1 (key/d half).
// Double-buffered 64-key K/V tiles via cp.async.
// ===========================================================================
// byte offsets
#define SQB   0                        // 128 x 272B = 34816
#define SKBb(b) (34816 + (b) * 17408)  // 2 x 64x272B
#define SVBb(b) (69632 + (b) * 17408)  // 2 x 64x272B
#define SPB   104448                   // 128 x 144B = 18432
#define FSMB  122880                   // fp32 stats
// float indices within fsm
#define AMI 0       // [128]
#define ALI 128     // [128]
#define AAL 256     // [128]
#define APMX 384    // [2][128]
#define APSM 640    // [2][128]
#define ATTN2_SMEM_BYTES (122880 + 896 * 4)   // 126464

__global__ void __launch_bounds__(256, 1) attn_mma()
{
    extern __shared__ char smc[];
    const uint32_t sb = smem_u32(smc);
    float* fsm = (float*)(smc + FSMB);
    const int tid = threadIdx.x;
    const int warp = tid >> 5, lane = tid & 31;
    const int wm = warp >> 1, wn = warp & 1;
    const int g = lane >> 2, tig = lane & 3;
    const int lrow = lane & 15, lcol = (lane >> 4) * 16;
    const int qt = blockIdx.x, hh = blockIdx.y, bb = blockIdx.z;
    const int bh = bb * 16 + hh, q0 = qt * 128;
    const int arow = wm * 32;              // 32 q-rows per warp (rg 0..1 x 16)

    const __half* qbase = g_qh + (size_t)bh * 512 * 128;
    const __half* kbase = g_kh + (size_t)bh * 512 * 128;
    const __half* vbase = g_vh + (size_t)bh * 512 * 128;

    // cp.async 64x128-half tile (4 iters) into padded smem (row stride 272B)
    auto stage = [&](uint32_t dstB, const __half* src) {
#pragma unroll
        for (int it = 0; it < 4; it++) {
            const int p = tid + it * 256;
            const int row = p >> 4, ch = p & 15;
            CP_ASYNC16(sb + dstB + row * 272 + ch * 16,
                       src + row * 128 + ch * 8);
        }
    };
    // Q: 128x128-half tile (8 iters)
    {
        const __half* src = qbase + (size_t)q0 * 128;
#pragma unroll
        for (int it = 0; it < 8; it++) {
            const int p = tid + it * 256;
            const int row = p >> 4, ch = p & 15;
            CP_ASYNC16(sb + SQB + row * 272 + ch * 16,
                       src + row * 128 + ch * 8);
        }
    }
    const int nkt = 2 * qt + 2;
    stage(SKBb(0), kbase);
    stage(SVBb(0), vbase);
    CP_COMMIT();
    if (nkt > 1) {
        stage(SKBb(1), kbase + 64 * 128);
        stage(SVBb(1), vbase + 64 * 128);
        CP_COMMIT();
    }

    if (tid < 128) { fsm[AMI + tid] = -1e30f; fsm[ALI + tid] = 0.f; }

    float o[2][8][4];
#pragma unroll
    for (int rg = 0; rg < 2; rg++)
#pragma unroll
        for (int i = 0; i < 8; i++)
#pragma unroll
            for (int q = 0; q < 4; q++) o[rg][i][q] = 0.f;

    for (int kt = 0; kt < nkt; kt++) {
        const int buf = kt & 1;
        if (kt < nkt - 1) { CP_WAIT1(); } else { CP_WAIT0(); }
        __syncthreads();

        // ---- S = Q K^T ----
        float sacc[2][4][4];
#pragma unroll
        for (int rg = 0; rg < 2; rg++)
#pragma unroll
            for (int nf = 0; nf < 4; nf++)
#pragma unroll
                for (int q = 0; q < 4; q++) sacc[rg][nf][q] = 0.f;

#pragma unroll
        for (int dc = 0; dc < 8; dc++) {
            uint32_t bf[2][4];
#pragma unroll
            for (int nb = 0; nb < 2; nb++)
                LDMX4(bf[nb], sb + SKBb(buf) +
                      (uint32_t)((wn * 32 + nb * 16 + lrow) * 272 + dc * 32 + lcol));
#pragma unroll
            for (int rg = 0; rg < 2; rg++) {
                uint32_t a[4];
                LDMX4(a, sb + SQB +
                      (uint32_t)((arow + rg * 16 + lrow) * 272 + dc * 32 + lcol));
#pragma unroll
                for (int nb = 0; nb < 2; nb++)
#pragma unroll
                    for (int i = 0; i < 2; i++) {
                        const int nf = nb * 2 + i;
                        MMA_F16(sacc[rg][nf], a[0], a[1], a[2], a[3],
                                bf[nb][i], bf[nb][i + 2]);
                    }
            }
        }

        // ---- causal mask (only where key tile can exceed q rows) ----
        if (kt >= 2 * qt) {
            const int kbase0 = kt * 64;
#pragma unroll
            for (int rg = 0; rg < 2; rg++) {
                const int lrA = q0 + arow + rg * 16 + g, lrB = lrA + 8;
#pragma unroll
                for (int nf = 0; nf < 4; nf++) {
                    const int lc = kbase0 + wn * 32 + nf * 8 + 2 * tig;
                    if (lc > lrA)     sacc[rg][nf][0] = -1e30f;
                    if (lc + 1 > lrA) sacc[rg][nf][1] = -1e30f;
                    if (lc > lrB)     sacc[rg][nf][2] = -1e30f;
                    if (lc + 1 > lrB) sacc[rg][nf][3] = -1e30f;
                }
            }
        }

        // ---- row max (per rg) ----
#pragma unroll
        for (int rg = 0; rg < 2; rg++) {
            float mA = -1e30f, mB = -1e30f;
#pragma unroll
            for (int nf = 0; nf < 4; nf++) {
                mA = fmaxf(mA, fmaxf(sacc[rg][nf][0], sacc[rg][nf][1]));
                mB = fmaxf(mB, fmaxf(sacc[rg][nf][2], sacc[rg][nf][3]));
            }
            mA = fmaxf(mA, __shfl_xor_sync(0xffffffffu, mA, 1));
            mA = fmaxf(mA, __shfl_xor_sync(0xffffffffu, mA, 2));
            mB = fmaxf(mB, __shfl_xor_sync(0xffffffffu, mB, 1));
            mB = fmaxf(mB, __shfl_xor_sync(0xffffffffu, mB, 2));
            if (tig == 0) {
                fsm[APMX + wn * 128 + arow + rg * 16 + g] = mA;
                fsm[APMX + wn * 128 + arow + rg * 16 + g + 8] = mB;
            }
        }
        __syncthreads();
        if (tid < 128) {
            const float mnew = fmaxf(fsm[AMI + tid],
                                     fmaxf(fsm[APMX + tid], fsm[APMX + 128 + tid]));
            fsm[AAL + tid] = __expf(fsm[AMI + tid] - mnew);
            fsm[AMI + tid] = mnew;
        }
        __syncthreads();

        // ---- p = exp(s - m), write P (fp16), row sums, rescale O ----
#pragma unroll
        for (int rg = 0; rg < 2; rg++) {
            const int rA = arow + rg * 16 + g, rB = rA + 8;
            const float mnA = fsm[AMI + rA], mnB = fsm[AMI + rB];
            const float alA = fsm[AAL + rA], alB = fsm[AAL + rB];
            float sumA = 0.f, sumB = 0.f;
#pragma unroll
            for (int nf = 0; nf < 4; nf++) {
                const float p0 = __expf(sacc[rg][nf][0] - mnA);
                const float p1 = __expf(sacc[rg][nf][1] - mnA);
                const float p2 = __expf(sacc[rg][nf][2] - mnB);
                const float p3 = __expf(sacc[rg][nf][3] - mnB);
                sumA += p0 + p1; sumB += p2 + p3;
                const int col = wn * 32 + nf * 8 + 2 * tig;
                *(__half2*)(smc + SPB + (rA * 72 + col) * 2) = __floats2half2_rn(p0, p1);
                *(__half2*)(smc + SPB + (rB * 72 + col) * 2) = __floats2half2_rn(p2, p3);
            }
            sumA += __shfl_xor_sync(0xffffffffu, sumA, 1);
            sumA += __shfl_xor_sync(0xffffffffu, sumA, 2);
            sumB += __shfl_xor_sync(0xffffffffu, sumB, 1);
            sumB += __shfl_xor_sync(0xffffffffu, sumB, 2);
            if (tig == 0) {
                fsm[APSM + wn * 128 + rA] = sumA;
                fsm[APSM + wn * 128 + rB] = sumB;
            }
#pragma unroll
            for (int nf2 = 0; nf2 < 8; nf2++) {
                o[rg][nf2][0] *= alA; o[rg][nf2][1] *= alA;
                o[rg][nf2][2] *= alB; o[rg][nf2][3] *= alB;
            }
        }
        __syncthreads();
        if (tid < 128)
            fsm[ALI + tid] = fsm[ALI + tid] * fsm[AAL + tid]
                           + fsm[APSM + tid] + fsm[APSM + 128 + tid];

        // ---- O += P @ V (V via ldmatrix.trans) ----
#pragma unroll
        for (int kc = 0; kc < 4; kc++) {
            uint32_t a[2][4];
#pragma unroll
            for (int rg = 0; rg < 2; rg++)
                LDMX4(a[rg], sb + SPB +
                      (uint32_t)((arow + rg * 16 + lrow) * 144 + kc * 32 + lcol));
#pragma unroll
            for (int dblk = 0; dblk < 4; dblk++) {
                uint32_t bf[4];
                LDMX4T(bf, sb + SVBb(buf) +
                       (uint32_t)((kc * 16 + lrow) * 272 + wn * 128 + dblk * 32 + lcol));
#pragma unroll
                for (int rg = 0; rg < 2; rg++) {
                    MMA_F16(o[rg][dblk * 2],     a[rg][0], a[rg][1], a[rg][2], a[rg][3],
                            bf[0], bf[1]);
                    MMA_F16(o[rg][dblk * 2 + 1], a[rg][0], a[rg][1], a[rg][2], a[rg][3],
                            bf[2], bf[3]);
                }
            }
        }
        __syncthreads();   // all reads of buf done -> safe to refill

        if (kt + 2 < nkt) {
            const int knext = (kt + 2) * 64;
            stage(SKBb(buf), kbase + (size_t)knext * 128);
            stage(SVBb(buf), vbase + (size_t)knext * 128);
            CP_COMMIT();
        }
    }

    // ---- epilogue: normalize, convert fp16, write g_yh ----
#pragma unroll
    for (int rg = 0; rg < 2; rg++) {
        const int rA = arow + rg * 16 + g, rB = rA + 8;
        const float invA = 1.f / fsm[ALI + rA];
        const float invB = 1.f / fsm[ALI + rB];
        const int tA = q0 + rA, tB = q0 + rB;
#pragma unroll
        for (int nf2 = 0; nf2 < 8; nf2++) {
            const int d = wn * 64 + nf2 * 8 + 2 * tig;
            *(__half2*)&g_yh[((size_t)bb * 512 + tA) * 2048 + hh * 128 + d] =
                __floats2half2_rn(o[rg][nf2][0] * invA, o[rg][nf2][1] * invA);
            *(__half2*)&g_yh[((size_t)bb * 512 + tB) * 2048 + hh * 128 + d] =
                __floats2half2_rn(o[rg][nf2][2] * invB, o[rg][nf2][3] * invB);
        }
    }
}

// ---------------------------------------------------------------------------
extern "C" void kernel_launch(void* const* d_in, const int* in_sizes, int n_in,
                              void* d_out, int out_size)
{
    (void)in_sizes; (void)n_in; (void)out_size;
    const float* x     = (const float*)d_in[0];
    const float* w_qkv = (const float*)d_in[1];
    const float* w_out = (const float*)d_in[2];
    float* out = (float*)d_out;

    __half *xh_ptr, *wqh_ptr, *woh_ptr, *yh_ptr;
    cudaGetSymbolAddress((void**)&xh_ptr,  g_xh);
    cudaGetSymbolAddress((void**)&wqh_ptr, g_wqh);
    cudaGetSymbolAddress((void**)&woh_ptr, g_woh);
    cudaGetSymbolAddress((void**)&yh_ptr,  g_yh);

    cudaFuncSetAttribute(gemm_h<1>, cudaFuncAttributeMaxDynamicSharedMemorySize, GEMM_SMEM_BYTES);
    cudaFuncSetAttribute(gemm_h<0>, cudaFuncAttributeMaxDynamicSharedMemorySize, GEMM_SMEM_BYTES);
    cudaFuncSetAttribute(attn_mma, cudaFuncAttributeMaxDynamicSharedMemorySize, ATTN2_SMEM_BYTES);

    // 0) convert inputs to fp16 + rope tables
    to_half<<<(8388608 + 255) / 256, 256>>>(x, xh_ptr, 8388608);
    to_half<<<(3145728 + 255) / 256, 256>>>(w_qkv, wqh_ptr, 3145728);
    to_half<<<(1048576 + 255) / 256, 256>>>(w_out, woh_ptr, 1048576);
    build_tables<<<64, 256>>>();

    // 1) QKV projection (fp16 mma; q/k/v fp16 scatter)
    {
        dim3 grid(6144 / 128, 16384 / 128);
        gemm_h<1><<<grid, 256, GEMM_SMEM_BYTES>>>(xh_ptr, wqh_ptr, nullptr, 16384, 6144, 2048);
    }
    // 1.5) in-place rope (+scale) on fp16 q, k
    {
        dim3 grid(128, 512, 2);
        rope_round<<<grid, 256>>>();
    }
    // 2) Attention (fp16 flash, Tq=128)
    {
        dim3 grid(4, 16, 32);
        attn_mma<<<grid, 256, ATTN2_SMEM_BYTES>>>();
    }
    // 3) Output projection (fp16 mma, fp32 out)
    {
        dim3 grid(2048 / 128, 16384 / 128);
        gemm_h<0><<<grid, 256, GEMM_SMEM_BYTES>>>(yh_ptr, woh_ptr, out, 16384, 2048, 2048);
    }
}

// round 13
// speedup vs baseline: 1.9360x; 1.0240x over previous
#include <cuda_runtime.h>
#include <cuda_fp16.h>
#include <math.h>
#include <cstdint>

// Shapes: x[32,512,2048] f32, w_qkv[6144,2048], w_out[2048,2048], out[32,512,2048]

// Scratch (device globals: allocation-free per harness rules)
__device__ __half g_qh[32L * 16 * 512 * 128];   // [B,H,T,D] fp16; rope applied in-place
__device__ __half g_kh[32L * 16 * 512 * 128];
__device__ __half g_vh[32L * 16 * 512 * 128];
__device__ __half g_yh[32L * 512 * 2048];       // [B,T,C] attn out fp16
__device__ __half g_xh[32L * 512 * 2048];       // x fp16
__device__ __half g_wqh[6144L * 2048];          // w_qkv fp16
__device__ __half g_woh[2048L * 2048];          // w_out fp16
__device__ float  g_cos[512 * 32];
__device__ float  g_sin[512 * 32];

// ===========================================================================
// Helpers
// ===========================================================================
__device__ __forceinline__ uint32_t smem_u32(const void* p) {
    uint32_t a;
    asm("{ .reg .u64 t; cvta.to.shared.u64 t, %1; cvt.u32.u64 %0, t; }" : "=r"(a) : "l"(p));
    return a;
}
__device__ __forceinline__ uint32_t swz(uint32_t off) { return off ^ ((off >> 3) & 0x70); }

#define CP_ASYNC16(dst, src) \
    asm volatile("cp.async.cg.shared.global [%0], [%1], 16;" :: "r"(dst), "l"(src))
#define CP_COMMIT() asm volatile("cp.async.commit_group;" ::: "memory")
#define CP_WAIT1() asm volatile("cp.async.wait_group 1;" ::: "memory")
#define CP_WAIT0() asm volatile("cp.async.wait_group 0;" ::: "memory")

#define MMA_F16(c, A0, A1, A2, A3, B0, B1) \
    asm volatile("mma.sync.aligned.m16n8k16.row.col.f32.f16.f16.f32 " \
        "{%0,%1,%2,%3},{%4,%5,%6,%7},{%8,%9},{%0,%1,%2,%3};" \
        : "+f"((c)[0]), "+f"((c)[1]), "+f"((c)[2]), "+f"((c)[3]) \
        : "r"(A0), "r"(A1), "r"(A2), "r"(A3), "r"(B0), "r"(B1))

#define LDMX4(r, addr) \
    asm volatile("ldmatrix.sync.aligned.m8n8.x4.shared.b16 {%0,%1,%2,%3}, [%4];" \
        : "=r"((r)[0]), "=r"((r)[1]), "=r"((r)[2]), "=r"((r)[3]) : "r"(addr))
#define LDMX4T(r, addr) \
    asm volatile("ldmatrix.sync.aligned.m8n8.x4.trans.shared.b16 {%0,%1,%2,%3}, [%4];" \
        : "=r"((r)[0]), "=r"((r)[1]), "=r"((r)[2]), "=r"((r)[3]) : "r"(addr))

// ===========================================================================
// Merged prep: f32->f16 of x, w_qkv, w_out + rope tables. One launch.
// ===========================================================================
#define N4_X  8388608
#define N4_WQ 3145728
#define N4_WO 1048576
#define N4_TOTAL (N4_X + N4_WQ + N4_WO)

__global__ void prep_all(const float* __restrict__ x,
                         const float* __restrict__ wq,
                         const float* __restrict__ wo)
{
    const int i = blockIdx.x * blockDim.x + threadIdx.x;
    if (i < 512 * 32) {
        const int t = i >> 5, j = i & 31;
        const double freq = pow(10000.0, -(double)j / 32.0);
        const double ang = (double)t * freq;
        g_cos[i] = (float)cos(ang);
        g_sin[i] = (float)sin(ang);
    }
    if (i >= N4_TOTAL) return;
    const float* in;
    __half* out;
    int idx = i;
    if (idx < N4_X) { in = x; out = g_xh; }
    else if (idx < N4_X + N4_WQ) { idx -= N4_X; in = wq; out = g_wqh; }
    else { idx -= N4_X + N4_WQ; in = wo; out = g_woh; }
    const float4 v = ((const float4*)in)[idx];
    ((__half2*)out)[idx * 2]     = __floats2half2_rn(v.x, v.y);
    ((__half2*)out)[idx * 2 + 1] = __floats2half2_rn(v.z, v.w);
}

// ===========================================================================
// In-place rope on fp16 q (plus 1/sqrt(D) scale) and k.
// Block 256 = 4 rows x 64 thr. Grid (128 t-groups, 512 bh, 2 sel).
// ===========================================================================
__global__ void __launch_bounds__(256) rope_round()
{
    const int tid = threadIdx.x;
    const int s = tid & 63;
    const int t = blockIdx.x * 4 + (tid >> 6);
    const int bh = blockIdx.y;
    const int sel = blockIdx.z;
    __half* p = (sel ? g_kh : g_qh) + ((size_t)bh * 512 + t) * 128;
    const float scale = sel ? 1.0f : 0.08838834764831845f;

    if (s < 32) {
        const float c = g_cos[t * 32 + s], si = g_sin[t * 32 + s];
        const float x1 = __half2float(p[s]), x2 = __half2float(p[s + 32]);
        p[s]      = __float2half_rn((x1 * c - x2 * si) * scale);
        p[s + 32] = __float2half_rn((x2 * c + x1 * si) * scale);
    } else if (sel == 0) {
        const int d1 = s + 32, d2 = s + 64;
        p[d1] = __float2half_rn(__half2float(p[d1]) * scale);
        p[d2] = __float2half_rn(__half2float(p[d2]) * scale);
    }
}

// ===========================================================================
// fp16 mma.sync GEMM: C[m,n] = sum_k A[m,k]*B[n,k], fp32 accumulate.
// 128x128 CTA tile, BK=64 halfs, 4 warps (2x2), warp tile 64x64,
// 128 threads, 2-stage cp.async, 2 CTA/SM (8 warps/SM, same occupancy).
// MODE 0: fp32 row-major store. MODE 1: scatter q/k/v fp16 [B,H,T,D].
// ===========================================================================
#define GEMM_SMEM_BYTES 65536

template <int MODE>
__global__ void __launch_bounds__(128, 2) gemm_h(
    const __half* __restrict__ A, const __half* __restrict__ Bm,
    float* __restrict__ Cout, int M, int N, int K)
{
    extern __shared__ char smraw[];
    const uint32_t sb = smem_u32(smraw);
    const int tid = threadIdx.x;
    const int warp = tid >> 5, lane = tid & 31;
    const int wm = warp >> 1, wn = warp & 1;   // 2x2 warps, 64x64 each
    const int m0 = blockIdx.y * 128, n0 = blockIdx.x * 128;
    const int lrow = lane & 15, lcol = (lane >> 4) * 16;

    float acc[4][8][4];
#pragma unroll
    for (int i = 0; i < 4; i++)
#pragma unroll
        for (int j = 0; j < 8; j++)
#pragma unroll
            for (int q = 0; q < 4; q++) acc[i][j][q] = 0.f;

    const int nch = K / 64;

    auto load_chunk = [&](int c, int buf) {
        const int k0 = c * 64;
        const uint32_t abase = sb + buf * 32768;
        const uint32_t bbase = abase + 16384;
#pragma unroll
        for (int it = 0; it < 8; it++) {
            const int t = tid + it * 128;
            const int row = t >> 3, ch = t & 7;
            CP_ASYNC16(abase + swz((uint32_t)(row * 128 + ch * 16)),
                       A + (size_t)(m0 + row) * K + k0 + ch * 8);
        }
#pragma unroll
        for (int it = 0; it < 8; it++) {
            const int t = tid + it * 128;
            const int row = t >> 3, ch = t & 7;
            CP_ASYNC16(bbase + swz((uint32_t)(row * 128 + ch * 16)),
                       Bm + (size_t)(n0 + row) * K + k0 + ch * 8);
        }
    };

    load_chunk(0, 0);
    CP_COMMIT();

    for (int c = 0; c < nch; c++) {
        const int buf = c & 1;
        const bool has_next = (c + 1 < nch);
        if (has_next) {
            load_chunk(c + 1, (c + 1) & 1);
            CP_COMMIT();
            CP_WAIT1();
        } else {
            CP_WAIT0();
        }
        __syncthreads();

        const uint32_t abase = sb + buf * 32768;
        const uint32_t bbase = abase + 16384;

#pragma unroll
        for (int ks = 0; ks < 4; ks++) {
            uint32_t a[4][4], b[4][4];
#pragma unroll
            for (int mf = 0; mf < 4; mf++) {
                const int row = wm * 64 + mf * 16 + lrow;
                LDMX4(a[mf], abase + swz((uint32_t)(row * 128 + ks * 32 + lcol)));
            }
#pragma unroll
            for (int nb = 0; nb < 4; nb++) {
                const int row = wn * 64 + nb * 16 + lrow;
                LDMX4(b[nb], bbase + swz((uint32_t)(row * 128 + ks * 32 + lcol)));
            }
#pragma unroll
            for (int mf = 0; mf < 4; mf++)
#pragma unroll
                for (int nf = 0; nf < 8; nf++) {
                    const int nb = nf >> 1, i = nf & 1;
                    MMA_F16(acc[mf][nf], a[mf][0], a[mf][1], a[mf][2], a[mf][3],
                            b[nb][i], b[nb][i + 2]);
                }
        }
        __syncthreads();
    }

    const int g = lane >> 2, tig = lane & 3;
    if (MODE == 0) {
#pragma unroll
        for (int mf = 0; mf < 4; mf++) {
            const int mA = m0 + wm * 64 + mf * 16 + g;
#pragma unroll
            for (int nf = 0; nf < 8; nf++) {
                const int nn = n0 + wn * 64 + nf * 8 + tig * 2;
                *(float2*)(Cout + (size_t)mA * N + nn) =
                    make_float2(acc[mf][nf][0], acc[mf][nf][1]);
                *(float2*)(Cout + (size_t)(mA + 8) * N + nn) =
                    make_float2(acc[mf][nf][2], acc[mf][nf][3]);
            }
        }
    } else {
        const int which = n0 >> 11;
        const int h = (n0 & 2047) >> 7;
        __half* basep = (which == 0) ? g_qh : (which == 1) ? g_kh : g_vh;
#pragma unroll
        for (int mf = 0; mf < 4; mf++) {
            const int mA = m0 + wm * 64 + mf * 16 + g;
            const int bA = mA >> 9, tA = mA & 511;
            const int mB = mA + 8;
            const int bB = mB >> 9, tB = mB & 511;
#pragma unroll
            for (int nf = 0; nf < 8; nf++) {
                const int d = wn * 64 + nf * 8 + tig * 2;
                const size_t iA = ((size_t)(bA * 16 + h) * 512 + tA) * 128 + d;
                const size_t iB = ((size_t)(bB * 16 + h) * 512 + tB) * 128 + d;
                *(__half2*)&basep[iA] = __floats2half2_rn(acc[mf][nf][0], acc[mf][nf][1]);
                *(__half2*)&basep[iB] = __floats2half2_rn(acc[mf][nf][2], acc[mf][nf][3]);
            }
        }
    }
}

// ===========================================================================
// fp16 tensor-core flash attention, Tq = 128 (unchanged from R12).
// 8 warps: wm 0..3 (32 q-rows via rg 0..1), wn 0..1 (key/d half).
// Double-buffered 64-key K/V tiles via cp.async.
// ===========================================================================
// byte offsets
#define SQB   0                        // 128 x 272B = 34816
#define SKBb(b) (34816 + (b) * 17408)  // 2 x 64x272B
#define SVBb(b) (69632 + (b) * 17408)  // 2 x 64x272B
#define SPB   104448                   // 128 x 144B = 18432
#define FSMB  122880                   // fp32 stats
// float indices within fsm
#define AMI 0       // [128]
#define ALI 128     // [128]
#define AAL 256     // [128]
#define APMX 384    // [2][128]
#define APSM 640    // [2][128]
#define ATTN2_SMEM_BYTES (122880 + 896 * 4)   // 126464

__global__ void __launch_bounds__(256, 1) attn_mma()
{
    extern __shared__ char smc[];
    const uint32_t sb = smem_u32(smc);
    float* fsm = (float*)(smc + FSMB);
    const int tid = threadIdx.x;
    const int warp = tid >> 5, lane = tid & 31;
    const int wm = warp >> 1, wn = warp & 1;
    const int g = lane >> 2, tig = lane & 3;
    const int lrow = lane & 15, lcol = (lane >> 4) * 16;
    const int qt = blockIdx.x, hh = blockIdx.y, bb = blockIdx.z;
    const int bh = bb * 16 + hh, q0 = qt * 128;
    const int arow = wm * 32;

    const __half* qbase = g_qh + (size_t)bh * 512 * 128;
    const __half* kbase = g_kh + (size_t)bh * 512 * 128;
    const __half* vbase = g_vh + (size_t)bh * 512 * 128;

    auto stage = [&](uint32_t dstB, const __half* src) {
#pragma unroll
        for (int it = 0; it < 4; it++) {
            const int p = tid + it * 256;
            const int row = p >> 4, ch = p & 15;
            CP_ASYNC16(sb + dstB + row * 272 + ch * 16,
                       src + row * 128 + ch * 8);
        }
    };
    {
        const __half* src = qbase + (size_t)q0 * 128;
#pragma unroll
        for (int it = 0; it < 8; it++) {
            const int p = tid + it * 256;
            const int row = p >> 4, ch = p & 15;
            CP_ASYNC16(sb + SQB + row * 272 + ch * 16,
                       src + row * 128 + ch * 8);
        }
    }
    const int nkt = 2 * qt + 2;
    stage(SKBb(0), kbase);
    stage(SVBb(0), vbase);
    CP_COMMIT();
    if (nkt > 1) {
        stage(SKBb(1), kbase + 64 * 128);
        stage(SVBb(1), vbase + 64 * 128);
        CP_COMMIT();
    }

    if (tid < 128) { fsm[AMI + tid] = -1e30f; fsm[ALI + tid] = 0.f; }

    float o[2][8][4];
#pragma unroll
    for (int rg = 0; rg < 2; rg++)
#pragma unroll
        for (int i = 0; i < 8; i++)
#pragma unroll
            for (int q = 0; q < 4; q++) o[rg][i][q] = 0.f;

    for (int kt = 0; kt < nkt; kt++) {
        const int buf = kt & 1;
        if (kt < nkt - 1) { CP_WAIT1(); } else { CP_WAIT0(); }
        __syncthreads();

        float sacc[2][4][4];
#pragma unroll
        for (int rg = 0; rg < 2; rg++)
#pragma unroll
            for (int nf = 0; nf < 4; nf++)
#pragma unroll
                for (int q = 0; q < 4; q++) sacc[rg][nf][q] = 0.f;

#pragma unroll
        for (int dc = 0; dc < 8; dc++) {
            uint32_t bf[2][4];
#pragma unroll
            for (int nb = 0; nb < 2; nb++)
                LDMX4(bf[nb], sb + SKBb(buf) +
                      (uint32_t)((wn * 32 + nb * 16 + lrow) * 272 + dc * 32 + lcol));
#pragma unroll
            for (int rg = 0; rg < 2; rg++) {
                uint32_t a[4];
                LDMX4(a, sb + SQB +
                      (uint32_t)((arow + rg * 16 + lrow) * 272 + dc * 32 + lcol));
#pragma unroll
                for (int nb = 0; nb < 2; nb++)
#pragma unroll
                    for (int i = 0; i < 2; i++) {
                        const int nf = nb * 2 + i;
                        MMA_F16(sacc[rg][nf], a[0], a[1], a[2], a[3],
                                bf[nb][i], bf[nb][i + 2]);
                    }
            }
        }

        if (kt >= 2 * qt) {
            const int kbase0 = kt * 64;
#pragma unroll
            for (int rg = 0; rg < 2; rg++) {
                const int lrA = q0 + arow + rg * 16 + g, lrB = lrA + 8;
#pragma unroll
                for (int nf = 0; nf < 4; nf++) {
                    const int lc = kbase0 + wn * 32 + nf * 8 + 2 * tig;
                    if (lc > lrA)     sacc[rg][nf][0] = -1e30f;
                    if (lc + 1 > lrA) sacc[rg][nf][1] = -1e30f;
                    if (lc > lrB)     sacc[rg][nf][2] = -1e30f;
                    if (lc + 1 > lrB) sacc[rg][nf][3] = -1e30f;
                }
            }
        }

#pragma unroll
        for (int rg = 0; rg < 2; rg++) {
            float mA = -1e30f, mB = -1e30f;
#pragma unroll
            for (int nf = 0; nf < 4; nf++) {
                mA = fmaxf(mA, fmaxf(sacc[rg][nf][0], sacc[rg][nf][1]));
                mB = fmaxf(mB, fmaxf(sacc[rg][nf][2], sacc[rg][nf][3]));
            }
            mA = fmaxf(mA, __shfl_xor_sync(0xffffffffu, mA, 1));
            mA = fmaxf(mA, __shfl_xor_sync(0xffffffffu, mA, 2));
            mB = fmaxf(mB, __shfl_xor_sync(0xffffffffu, mB, 1));
            mB = fmaxf(mB, __shfl_xor_sync(0xffffffffu, mB, 2));
            if (tig == 0) {
                fsm[APMX + wn * 128 + arow + rg * 16 + g] = mA;
                fsm[APMX + wn * 128 + arow + rg * 16 + g + 8] = mB;
            }
        }
        __syncthreads();
        if (tid < 128) {
            const float mnew = fmaxf(fsm[AMI + tid],
                                     fmaxf(fsm[APMX + tid], fsm[APMX + 128 + tid]));
            fsm[AAL + tid] = __expf(fsm[AMI + tid] - mnew);
            fsm[AMI + tid] = mnew;
        }
        __syncthreads();

#pragma unroll
        for (int rg = 0; rg < 2; rg++) {
            const int rA = arow + rg * 16 + g, rB = rA + 8;
            const float mnA = fsm[AMI + rA], mnB = fsm[AMI + rB];
            const float alA = fsm[AAL + rA], alB = fsm[AAL + rB];
            float sumA = 0.f, sumB = 0.f;
#pragma unroll
            for (int nf = 0; nf < 4; nf++) {
                const float p0 = __expf(sacc[rg][nf][0] - mnA);
                const float p1 = __expf(sacc[rg][nf][1] - mnA);
                const float p2 = __expf(sacc[rg][nf][2] - mnB);
                const float p3 = __expf(sacc[rg][nf][3] - mnB);
                sumA += p0 + p1; sumB += p2 + p3;
                const int col = wn * 32 + nf * 8 + 2 * tig;
                *(__half2*)(smc + SPB + (rA * 72 + col) * 2) = __floats2half2_rn(p0, p1);
                *(__half2*)(smc + SPB + (rB * 72 + col) * 2) = __floats2half2_rn(p2, p3);
            }
            sumA += __shfl_xor_sync(0xffffffffu, sumA, 1);
            sumA += __shfl_xor_sync(0xffffffffu, sumA, 2);
            sumB += __shfl_xor_sync(0xffffffffu, sumB, 1);
            sumB += __shfl_xor_sync(0xffffffffu, sumB, 2);
            if (tig == 0) {
                fsm[APSM + wn * 128 + rA] = sumA;
                fsm[APSM + wn * 128 + rB] = sumB;
            }
#pragma unroll
            for (int nf2 = 0; nf2 < 8; nf2++) {
                o[rg][nf2][0] *= alA; o[rg][nf2][1] *= alA;
                o[rg][nf2][2] *= alB; o[rg][nf2][3] *= alB;
            }
        }
        __syncthreads();
        if (tid < 128)
            fsm[ALI + tid] = fsm[ALI + tid] * fsm[AAL + tid]
                           + fsm[APSM + tid] + fsm[APSM + 128 + tid];

#pragma unroll
        for (int kc = 0; kc < 4; kc++) {
            uint32_t a[2][4];
#pragma unroll
            for (int rg = 0; rg < 2; rg++)
                LDMX4(a[rg], sb + SPB +
                      (uint32_t)((arow + rg * 16 + lrow) * 144 + kc * 32 + lcol));
#pragma unroll
            for (int dblk = 0; dblk < 4; dblk++) {
                uint32_t bf[4];
                LDMX4T(bf, sb + SVBb(buf) +
                       (uint32_t)((kc * 16 + lrow) * 272 + wn * 128 + dblk * 32 + lcol));
#pragma unroll
                for (int rg = 0; rg < 2; rg++) {
                    MMA_F16(o[rg][dblk * 2],     a[rg][0], a[rg][1], a[rg][2], a[rg][3],
                            bf[0], bf[1]);
                    MMA_F16(o[rg][dblk * 2 + 1], a[rg][0], a[rg][1], a[rg][2], a[rg][3],
                            bf[2], bf[3]);
                }
            }
        }
        __syncthreads();

        if (kt + 2 < nkt) {
            const int knext = (kt + 2) * 64;
            stage(SKBb(buf), kbase + (size_t)knext * 128);
            stage(SVBb(buf), vbase + (size_t)knext * 128);
            CP_COMMIT();
        }
    }

#pragma unroll
    for (int rg = 0; rg < 2; rg++) {
        const int rA = arow + rg * 16 + g, rB = rA + 8;
        const float invA = 1.f / fsm[ALI + rA];
        const float invB = 1.f / fsm[ALI + rB];
        const int tA = q0 + rA, tB = q0 + rB;
#pragma unroll
        for (int nf2 = 0; nf2 < 8; nf2++) {
            const int d = wn * 64 + nf2 * 8 + 2 * tig;
            *(__half2*)&g_yh[((size_t)bb * 512 + tA) * 2048 + hh * 128 + d] =
                __floats2half2_rn(o[rg][nf2][0] * invA, o[rg][nf2][1] * invA);
            *(__half2*)&g_yh[((size_t)bb * 512 + tB) * 2048 + hh * 128 + d] =
                __floats2half2_rn(o[rg][nf2][2] * invB, o[rg][nf2][3] * invB);
        }
    }
}

// ---------------------------------------------------------------------------
extern "C" void kernel_launch(void* const* d_in, const int* in_sizes, int n_in,
                              void* d_out, int out_size)
{
    (void)in_sizes; (void)n_in; (void)out_size;
    const float* x     = (const float*)d_in[0];
    const float* w_qkv = (const float*)d_in[1];
    const float* w_out = (const float*)d_in[2];
    float* out = (float*)d_out;

    __half *xh_ptr, *wqh_ptr, *woh_ptr, *yh_ptr;
    cudaGetSymbolAddress((void**)&xh_ptr,  g_xh);
    cudaGetSymbolAddress((void**)&wqh_ptr, g_wqh);
    cudaGetSymbolAddress((void**)&woh_ptr, g_woh);
    cudaGetSymbolAddress((void**)&yh_ptr,  g_yh);

    cudaFuncSetAttribute(gemm_h<1>, cudaFuncAttributeMaxDynamicSharedMemorySize, GEMM_SMEM_BYTES);
    cudaFuncSetAttribute(gemm_h<0>, cudaFuncAttributeMaxDynamicSharedMemorySize, GEMM_SMEM_BYTES);
    cudaFuncSetAttribute(attn_mma, cudaFuncAttributeMaxDynamicSharedMemorySize, ATTN2_SMEM_BYTES);

    // 0) merged prep: fp16 converts + rope tables (one launch)
    prep_all<<<(N4_TOTAL + 255) / 256, 256>>>(x, w_qkv, w_out);

    // 1) QKV projection (fp16 mma; q/k/v fp16 scatter)
    {
        dim3 grid(6144 / 128, 16384 / 128);
        gemm_h<1><<<grid, 128, GEMM_SMEM_BYTES>>>(xh_ptr, wqh_ptr, nullptr, 16384, 6144, 2048);
    }
    // 1.5) in-place rope (+scale) on fp16 q, k
    {
        dim3 grid(128, 512, 2);
        rope_round<<<grid, 256>>>();
    }
    // 2) Attention (fp16 flash, Tq=128)
    {
        dim3 grid(4, 16, 32);
        attn_mma<<<grid, 256, ATTN2_SMEM_BYTES>>>();
    }
    // 3) Output projection (fp16 mma, fp32 out)
    {
        dim3 grid(2048 / 128, 16384 / 128);
        gemm_h<0><<<grid, 128, GEMM_SMEM_BYTES>>>(yh_ptr, woh_ptr, out, 16384, 2048, 2048);
    }
}

// round 14
// speedup vs baseline: 1.9970x; 1.0315x over previous
#include <cuda_runtime.h>
#include <cuda_fp16.h>
#include <math.h>
#include <cstdint>

// Shapes: x[32,512,2048] f32, w_qkv[6144,2048], w_out[2048,2048], out[32,512,2048]

// Scratch (device globals: allocation-free per harness rules)
__device__ __half g_qh[32L * 16 * 512 * 128];   // [B,H,T,D] fp16; rope applied in-place
__device__ __half g_kh[32L * 16 * 512 * 128];
__device__ __half g_vh[32L * 16 * 512 * 128];
__device__ __half g_yh[32L * 512 * 2048];       // [B,T,C] attn out fp16
__device__ __half g_xh[32L * 512 * 2048];       // x fp16
__device__ __half g_wqh[6144L * 2048];          // w_qkv fp16
__device__ __half g_woh[2048L * 2048];          // w_out fp16
__device__ float  g_cos[512 * 32];
__device__ float  g_sin[512 * 32];

// ===========================================================================
// Helpers
// ===========================================================================
__device__ __forceinline__ uint32_t smem_u32(const void* p) {
    uint32_t a;
    asm("{ .reg .u64 t; cvta.to.shared.u64 t, %1; cvt.u32.u64 %0, t; }" : "=r"(a) : "l"(p));
    return a;
}
__device__ __forceinline__ uint32_t swz(uint32_t off) { return off ^ ((off >> 3) & 0x70); }

#define CP_ASYNC16(dst, src) \
    asm volatile("cp.async.cg.shared.global [%0], [%1], 16;" :: "r"(dst), "l"(src))
#define CP_COMMIT() asm volatile("cp.async.commit_group;" ::: "memory")
#define CP_WAIT1() asm volatile("cp.async.wait_group 1;" ::: "memory")
#define CP_WAIT0() asm volatile("cp.async.wait_group 0;" ::: "memory")

#define MMA_F16(c, A0, A1, A2, A3, B0, B1) \
    asm volatile("mma.sync.aligned.m16n8k16.row.col.f32.f16.f16.f32 " \
        "{%0,%1,%2,%3},{%4,%5,%6,%7},{%8,%9},{%0,%1,%2,%3};" \
        : "+f"((c)[0]), "+f"((c)[1]), "+f"((c)[2]), "+f"((c)[3]) \
        : "r"(A0), "r"(A1), "r"(A2), "r"(A3), "r"(B0), "r"(B1))

#define LDMX4(r, addr) \
    asm volatile("ldmatrix.sync.aligned.m8n8.x4.shared.b16 {%0,%1,%2,%3}, [%4];" \
        : "=r"((r)[0]), "=r"((r)[1]), "=r"((r)[2]), "=r"((r)[3]) : "r"(addr))
#define LDMX4T(r, addr) \
    asm volatile("ldmatrix.sync.aligned.m8n8.x4.trans.shared.b16 {%0,%1,%2,%3}, [%4];" \
        : "=r"((r)[0]), "=r"((r)[1]), "=r"((r)[2]), "=r"((r)[3]) : "r"(addr))

__device__ __forceinline__ uint32_t pack2(float a, float b) {
    const __half2 h = __floats2half2_rn(a, b);
    return *(const uint32_t*)&h;
}

// ===========================================================================
// Merged prep: f32->f16 of x, w_qkv, w_out + rope tables. One launch.
// ===========================================================================
#define N4_X  8388608
#define N4_WQ 3145728
#define N4_WO 1048576
#define N4_TOTAL (N4_X + N4_WQ + N4_WO)

__global__ void prep_all(const float* __restrict__ x,
                         const float* __restrict__ wq,
                         const float* __restrict__ wo)
{
    const int i = blockIdx.x * blockDim.x + threadIdx.x;
    if (i < 512 * 32) {
        const int t = i >> 5, j = i & 31;
        const double freq = pow(10000.0, -(double)j / 32.0);
        const double ang = (double)t * freq;
        g_cos[i] = (float)cos(ang);
        g_sin[i] = (float)sin(ang);
    }
    if (i >= N4_TOTAL) return;
    const float* in;
    __half* out;
    int idx = i;
    if (idx < N4_X) { in = x; out = g_xh; }
    else if (idx < N4_X + N4_WQ) { idx -= N4_X; in = wq; out = g_wqh; }
    else { idx -= N4_X + N4_WQ; in = wo; out = g_woh; }
    const float4 v = ((const float4*)in)[idx];
    ((__half2*)out)[idx * 2]     = __floats2half2_rn(v.x, v.y);
    ((__half2*)out)[idx * 2 + 1] = __floats2half2_rn(v.z, v.w);
}

// ===========================================================================
// In-place rope on fp16 q (plus 1/sqrt(D) scale) and k.
// ===========================================================================
__global__ void __launch_bounds__(256) rope_round()
{
    const int tid = threadIdx.x;
    const int s = tid & 63;
    const int t = blockIdx.x * 4 + (tid >> 6);
    const int bh = blockIdx.y;
    const int sel = blockIdx.z;
    __half* p = (sel ? g_kh : g_qh) + ((size_t)bh * 512 + t) * 128;
    const float scale = sel ? 1.0f : 0.08838834764831845f;

    if (s < 32) {
        const float c = g_cos[t * 32 + s], si = g_sin[t * 32 + s];
        const float x1 = __half2float(p[s]), x2 = __half2float(p[s + 32]);
        p[s]      = __float2half_rn((x1 * c - x2 * si) * scale);
        p[s + 32] = __float2half_rn((x2 * c + x1 * si) * scale);
    } else if (sel == 0) {
        const int d1 = s + 32, d2 = s + 64;
        p[d1] = __float2half_rn(__half2float(p[d1]) * scale);
        p[d2] = __float2half_rn(__half2float(p[d2]) * scale);
    }
}

// ===========================================================================
// fp16 mma.sync GEMM (R13 config, best known): 128x128 CTA tile, BK=64,
// 4 warps (2x2) x 64x64 warp tile, 128 threads, 2-stage cp.async, 2 CTA/SM.
// ===========================================================================
#define GEMM_SMEM_BYTES 65536

template <int MODE>
__global__ void __launch_bounds__(128, 2) gemm_h(
    const __half* __restrict__ A, const __half* __restrict__ Bm,
    float* __restrict__ Cout, int M, int N, int K)
{
    extern __shared__ char smraw[];
    const uint32_t sb = smem_u32(smraw);
    const int tid = threadIdx.x;
    const int warp = tid >> 5, lane = tid & 31;
    const int wm = warp >> 1, wn = warp & 1;
    const int m0 = blockIdx.y * 128, n0 = blockIdx.x * 128;
    const int lrow = lane & 15, lcol = (lane >> 4) * 16;

    float acc[4][8][4];
#pragma unroll
    for (int i = 0; i < 4; i++)
#pragma unroll
        for (int j = 0; j < 8; j++)
#pragma unroll
            for (int q = 0; q < 4; q++) acc[i][j][q] = 0.f;

    const int nch = K / 64;

    auto load_chunk = [&](int c, int buf) {
        const int k0 = c * 64;
        const uint32_t abase = sb + buf * 32768;
        const uint32_t bbase = abase + 16384;
#pragma unroll
        for (int it = 0; it < 8; it++) {
            const int t = tid + it * 128;
            const int row = t >> 3, ch = t & 7;
            CP_ASYNC16(abase + swz((uint32_t)(row * 128 + ch * 16)),
                       A + (size_t)(m0 + row) * K + k0 + ch * 8);
        }
#pragma unroll
        for (int it = 0; it < 8; it++) {
            const int t = tid + it * 128;
            const int row = t >> 3, ch = t & 7;
            CP_ASYNC16(bbase + swz((uint32_t)(row * 128 + ch * 16)),
                       Bm + (size_t)(n0 + row) * K + k0 + ch * 8);
        }
    };

    load_chunk(0, 0);
    CP_COMMIT();

    for (int c = 0; c < nch; c++) {
        const int buf = c & 1;
        const bool has_next = (c + 1 < nch);
        if (has_next) {
            load_chunk(c + 1, (c + 1) & 1);
            CP_COMMIT();
            CP_WAIT1();
        } else {
            CP_WAIT0();
        }
        __syncthreads();

        const uint32_t abase = sb + buf * 32768;
        const uint32_t bbase = abase + 16384;

#pragma unroll
        for (int ks = 0; ks < 4; ks++) {
            uint32_t a[4][4], b[4][4];
#pragma unroll
            for (int mf = 0; mf < 4; mf++) {
                const int row = wm * 64 + mf * 16 + lrow;
                LDMX4(a[mf], abase + swz((uint32_t)(row * 128 + ks * 32 + lcol)));
            }
#pragma unroll
            for (int nb = 0; nb < 4; nb++) {
                const int row = wn * 64 + nb * 16 + lrow;
                LDMX4(b[nb], bbase + swz((uint32_t)(row * 128 + ks * 32 + lcol)));
            }
#pragma unroll
            for (int mf = 0; mf < 4; mf++)
#pragma unroll
                for (int nf = 0; nf < 8; nf++) {
                    const int nb = nf >> 1, i = nf & 1;
                    MMA_F16(acc[mf][nf], a[mf][0], a[mf][1], a[mf][2], a[mf][3],
                            b[nb][i], b[nb][i + 2]);
                }
        }
        __syncthreads();
    }

    const int g = lane >> 2, tig = lane & 3;
    if (MODE == 0) {
#pragma unroll
        for (int mf = 0; mf < 4; mf++) {
            const int mA = m0 + wm * 64 + mf * 16 + g;
#pragma unroll
            for (int nf = 0; nf < 8; nf++) {
                const int nn = n0 + wn * 64 + nf * 8 + tig * 2;
                *(float2*)(Cout + (size_t)mA * N + nn) =
                    make_float2(acc[mf][nf][0], acc[mf][nf][1]);
                *(float2*)(Cout + (size_t)(mA + 8) * N + nn) =
                    make_float2(acc[mf][nf][2], acc[mf][nf][3]);
            }
        }
    } else {
        const int which = n0 >> 11;
        const int h = (n0 & 2047) >> 7;
        __half* basep = (which == 0) ? g_qh : (which == 1) ? g_kh : g_vh;
#pragma unroll
        for (int mf = 0; mf < 4; mf++) {
            const int mA = m0 + wm * 64 + mf * 16 + g;
            const int bA = mA >> 9, tA = mA & 511;
            const int mB = mA + 8;
            const int bB = mB >> 9, tB = mB & 511;
#pragma unroll
            for (int nf = 0; nf < 8; nf++) {
                const int d = wn * 64 + nf * 8 + tig * 2;
                const size_t iA = ((size_t)(bA * 16 + h) * 512 + tA) * 128 + d;
                const size_t iB = ((size_t)(bB * 16 + h) * 512 + tB) * 128 + d;
                *(__half2*)&basep[iA] = __floats2half2_rn(acc[mf][nf][0], acc[mf][nf][1]);
                *(__half2*)&basep[iB] = __floats2half2_rn(acc[mf][nf][2], acc[mf][nf][3]);
            }
        }
    }
}

// ===========================================================================
// Register-resident fp16 flash attention.
// Tq=64, 4 warps (16 q-rows each), each warp: full 64 keys x full 128 d.
// P stays in registers (QK C-frag == PV A-frag layout). Softmax warp-local.
// Double-buffered 64-key K/V via cp.async. 2 CTA/SM (85 KB smem).
// ===========================================================================
#define ASQ   0                        // 64 x 272B
#define ASK(b) (17408 + (b) * 17408)   // 2 x 64x272B
#define ASV(b) (52224 + (b) * 17408)   // 2 x 64x272B
#define ATTN2_SMEM_BYTES 87040

__global__ void __launch_bounds__(128, 2) attn_mma()
{
    extern __shared__ char smc[];
    const uint32_t sb = smem_u32(smc);
    const int tid = threadIdx.x;
    const int warp = tid >> 5, lane = tid & 31;
    const int g = lane >> 2, tig = lane & 3;
    const int lrow = lane & 15, lcol = (lane >> 4) * 16;
    const int qt = blockIdx.x, hh = blockIdx.y, bb = blockIdx.z;
    const int bh = bb * 16 + hh, q0 = qt * 64;
    const int arow = warp * 16;

    const __half* qbase = g_qh + (size_t)bh * 512 * 128;
    const __half* kbase = g_kh + (size_t)bh * 512 * 128;
    const __half* vbase = g_vh + (size_t)bh * 512 * 128;

    // stage a 64x128-half tile (row stride 272B), 128 threads x 8 iters
    auto stage = [&](uint32_t dstB, const __half* src) {
#pragma unroll
        for (int it = 0; it < 8; it++) {
            const int p = tid + it * 128;
            const int row = p >> 4, ch = p & 15;
            CP_ASYNC16(sb + dstB + row * 272 + ch * 16,
                       src + row * 128 + ch * 8);
        }
    };

    const int nkt = qt + 1;
    stage(ASQ, qbase + (size_t)q0 * 128);
    stage(ASK(0), kbase);
    stage(ASV(0), vbase);
    CP_COMMIT();
    if (nkt > 1) {
        stage(ASK(1), kbase + 64 * 128);
        stage(ASV(1), vbase + 64 * 128);
        CP_COMMIT();
    }

    float o[16][4];
#pragma unroll
    for (int i = 0; i < 16; i++)
#pragma unroll
        for (int q = 0; q < 4; q++) o[i][q] = 0.f;
    float mA = -1e30f, mB = -1e30f, lA = 0.f, lB = 0.f;

    for (int kt = 0; kt < nkt; kt++) {
        const int buf = kt & 1;
        if (kt < nkt - 1) { CP_WAIT1(); } else { CP_WAIT0(); }
        __syncthreads();

        // ---- S = Q K^T: 16 rows x 64 keys ----
        float sacc[8][4];
#pragma unroll
        for (int nf = 0; nf < 8; nf++)
#pragma unroll
            for (int q = 0; q < 4; q++) sacc[nf][q] = 0.f;

#pragma unroll
        for (int dc = 0; dc < 8; dc++) {
            uint32_t a[4];
            LDMX4(a, sb + ASQ + (uint32_t)((arow + lrow) * 272 + dc * 32 + lcol));
#pragma unroll
            for (int nb = 0; nb < 4; nb++) {
                uint32_t bf[4];
                LDMX4(bf, sb + ASK(buf) +
                      (uint32_t)((nb * 16 + lrow) * 272 + dc * 32 + lcol));
#pragma unroll
                for (int i = 0; i < 2; i++)
                    MMA_F16(sacc[nb * 2 + i], a[0], a[1], a[2], a[3],
                            bf[i], bf[i + 2]);
            }
        }

        // ---- causal mask (diagonal tile only) ----
        if (kt == qt) {
            const int lrA = arow + g, lrB = lrA + 8;
#pragma unroll
            for (int nf = 0; nf < 8; nf++) {
                const int lc = nf * 8 + 2 * tig;
                if (lc > lrA)     sacc[nf][0] = -1e30f;
                if (lc + 1 > lrA) sacc[nf][1] = -1e30f;
                if (lc > lrB)     sacc[nf][2] = -1e30f;
                if (lc + 1 > lrB) sacc[nf][3] = -1e30f;
            }
        }

        // ---- warp-local online softmax ----
        float mAn = -1e30f, mBn = -1e30f;
#pragma unroll
        for (int nf = 0; nf < 8; nf++) {
            mAn = fmaxf(mAn, fmaxf(sacc[nf][0], sacc[nf][1]));
            mBn = fmaxf(mBn, fmaxf(sacc[nf][2], sacc[nf][3]));
        }
        mAn = fmaxf(mAn, __shfl_xor_sync(0xffffffffu, mAn, 1));
        mAn = fmaxf(mAn, __shfl_xor_sync(0xffffffffu, mAn, 2));
        mBn = fmaxf(mBn, __shfl_xor_sync(0xffffffffu, mBn, 1));
        mBn = fmaxf(mBn, __shfl_xor_sync(0xffffffffu, mBn, 2));
        const float mAnew = fmaxf(mA, mAn), mBnew = fmaxf(mB, mBn);
        const float alA = __expf(mA - mAnew), alB = __expf(mB - mBnew);
        mA = mAnew; mB = mBnew;

        // p = exp(s - m); pack directly into PV A-fragments
        uint32_t pf[4][4];
        float sA = 0.f, sB = 0.f;
#pragma unroll
        for (int kc = 0; kc < 4; kc++) {
            const float p0 = __expf(sacc[2 * kc][0] - mA);
            const float p1 = __expf(sacc[2 * kc][1] - mA);
            const float p2 = __expf(sacc[2 * kc][2] - mB);
            const float p3 = __expf(sacc[2 * kc][3] - mB);
            const float p4 = __expf(sacc[2 * kc + 1][0] - mA);
            const float p5 = __expf(sacc[2 * kc + 1][1] - mA);
            const float p6 = __expf(sacc[2 * kc + 1][2] - mB);
            const float p7 = __expf(sacc[2 * kc + 1][3] - mB);
            sA += p0 + p1 + p4 + p5;
            sB += p2 + p3 + p6 + p7;
            pf[kc][0] = pack2(p0, p1);
            pf[kc][1] = pack2(p2, p3);
            pf[kc][2] = pack2(p4, p5);
            pf[kc][3] = pack2(p6, p7);
        }
        sA += __shfl_xor_sync(0xffffffffu, sA, 1);
        sA += __shfl_xor_sync(0xffffffffu, sA, 2);
        sB += __shfl_xor_sync(0xffffffffu, sB, 1);
        sB += __shfl_xor_sync(0xffffffffu, sB, 2);
        lA = lA * alA + sA;
        lB = lB * alB + sB;

#pragma unroll
        for (int i = 0; i < 16; i++) {
            o[i][0] *= alA; o[i][1] *= alA;
            o[i][2] *= alB; o[i][3] *= alB;
        }

        // ---- O += P @ V (V via ldmatrix.trans; note fp16 P from pack2) ----
#pragma unroll
        for (int kc = 0; kc < 4; kc++) {
#pragma unroll
            for (int dblk = 0; dblk < 8; dblk++) {
                uint32_t bf[4];
                LDMX4T(bf, sb + ASV(buf) +
                       (uint32_t)((kc * 16 + lrow) * 272 + dblk * 32 + lcol));
                MMA_F16(o[dblk * 2],     pf[kc][0], pf[kc][1], pf[kc][2], pf[kc][3],
                        bf[0], bf[1]);
                MMA_F16(o[dblk * 2 + 1], pf[kc][0], pf[kc][1], pf[kc][2], pf[kc][3],
                        bf[2], bf[3]);
            }
        }
        __syncthreads();   // all warps done with buf -> safe to refill

        if (kt + 2 < nkt) {
            const int knext = (kt + 2) * 64;
            stage(ASK(buf), kbase + (size_t)knext * 128);
            stage(ASV(buf), vbase + (size_t)knext * 128);
            CP_COMMIT();
        }
    }

    // ---- epilogue: normalize, convert fp16, write g_yh ----
    const float invA = 1.f / lA, invB = 1.f / lB;
    const int tA = q0 + arow + g, tB = tA + 8;
#pragma unroll
    for (int nf2 = 0; nf2 < 16; nf2++) {
        const int d = nf2 * 8 + 2 * tig;
        *(__half2*)&g_yh[((size_t)bb * 512 + tA) * 2048 + hh * 128 + d] =
            __floats2half2_rn(o[nf2][0] * invA, o[nf2][1] * invA);
        *(__half2*)&g_yh[((size_t)bb * 512 + tB) * 2048 + hh * 128 + d] =
            __floats2half2_rn(o[nf2][2] * invB, o[nf2][3] * invB);
    }
}

// ---------------------------------------------------------------------------
extern "C" void kernel_launch(void* const* d_in, const int* in_sizes, int n_in,
                              void* d_out, int out_size)
{
    (void)in_sizes; (void)n_in; (void)out_size;
    const float* x     = (const float*)d_in[0];
    const float* w_qkv = (const float*)d_in[1];
    const float* w_out = (const float*)d_in[2];
    float* out = (float*)d_out;

    __half *xh_ptr, *wqh_ptr, *woh_ptr, *yh_ptr;
    cudaGetSymbolAddress((void**)&xh_ptr,  g_xh);
    cudaGetSymbolAddress((void**)&wqh_ptr, g_wqh);
    cudaGetSymbolAddress((void**)&woh_ptr, g_woh);
    cudaGetSymbolAddress((void**)&yh_ptr,  g_yh);

    cudaFuncSetAttribute(gemm_h<1>, cudaFuncAttributeMaxDynamicSharedMemorySize, GEMM_SMEM_BYTES);
    cudaFuncSetAttribute(gemm_h<0>, cudaFuncAttributeMaxDynamicSharedMemorySize, GEMM_SMEM_BYTES);
    cudaFuncSetAttribute(attn_mma, cudaFuncAttributeMaxDynamicSharedMemorySize, ATTN2_SMEM_BYTES);

    // 0) merged prep
    prep_all<<<(N4_TOTAL + 255) / 256, 256>>>(x, w_qkv, w_out);

    // 1) QKV projection
    {
        dim3 grid(6144 / 128, 16384 / 128);
        gemm_h<1><<<grid, 128, GEMM_SMEM_BYTES>>>(xh_ptr, wqh_ptr, nullptr, 16384, 6144, 2048);
    }
    // 1.5) in-place rope (+scale)
    {
        dim3 grid(128, 512, 2);
        rope_round<<<grid, 256>>>();
    }
    // 2) Attention (register-resident flash, Tq=64, 2 CTA/SM)
    {
        dim3 grid(8, 16, 32);
        attn_mma<<<grid, 128, ATTN2_SMEM_BYTES>>>();
    }
    // 3) Output projection
    {
        dim3 grid(2048 / 128, 16384 / 128);
        gemm_h<0><<<grid, 128, GEMM_SMEM_BYTES>>>(yh_ptr, woh_ptr, out, 16384, 2048, 2048);
    }
}

// round 15
// speedup vs baseline: 2.0406x; 1.0218x over previous
#include <cuda_runtime.h>
#include <cuda_fp16.h>
#include <math.h>
#include <cstdint>

// Shapes: x[32,512,2048] f32, w_qkv[6144,2048], w_out[2048,2048], out[32,512,2048]

// Scratch (device globals: allocation-free per harness rules)
__device__ __half g_qh[32L * 16 * 512 * 128];   // [B,H,T,D] fp16, roped+scaled at gemm epilogue
__device__ __half g_kh[32L * 16 * 512 * 128];   // roped at gemm epilogue
__device__ __half g_vh[32L * 16 * 512 * 128];
__device__ __half g_yh[32L * 512 * 2048];       // [B,T,C] attn out fp16
__device__ __half g_xh[32L * 512 * 2048];       // x fp16
__device__ __half g_wqh[6144L * 2048];          // w_qkv fp16
__device__ __half g_woh[2048L * 2048];          // w_out fp16
__device__ float  g_cos[512 * 32];
__device__ float  g_sin[512 * 32];

// ===========================================================================
// Helpers
// ===========================================================================
__device__ __forceinline__ uint32_t smem_u32(const void* p) {
    uint32_t a;
    asm("{ .reg .u64 t; cvta.to.shared.u64 t, %1; cvt.u32.u64 %0, t; }" : "=r"(a) : "l"(p));
    return a;
}
__device__ __forceinline__ uint32_t swz(uint32_t off) { return off ^ ((off >> 3) & 0x70); }

#define CP_ASYNC16(dst, src) \
    asm volatile("cp.async.cg.shared.global [%0], [%1], 16;" :: "r"(dst), "l"(src))
#define CP_COMMIT() asm volatile("cp.async.commit_group;" ::: "memory")
#define CP_WAIT1() asm volatile("cp.async.wait_group 1;" ::: "memory")
#define CP_WAIT0() asm volatile("cp.async.wait_group 0;" ::: "memory")

#define MMA_F16(c, A0, A1, A2, A3, B0, B1) \
    asm volatile("mma.sync.aligned.m16n8k16.row.col.f32.f16.f16.f32 " \
        "{%0,%1,%2,%3},{%4,%5,%6,%7},{%8,%9},{%0,%1,%2,%3};" \
        : "+f"((c)[0]), "+f"((c)[1]), "+f"((c)[2]), "+f"((c)[3]) \
        : "r"(A0), "r"(A1), "r"(A2), "r"(A3), "r"(B0), "r"(B1))

#define LDMX4(r, addr) \
    asm volatile("ldmatrix.sync.aligned.m8n8.x4.shared.b16 {%0,%1,%2,%3}, [%4];" \
        : "=r"((r)[0]), "=r"((r)[1]), "=r"((r)[2]), "=r"((r)[3]) : "r"(addr))
#define LDMX4T(r, addr) \
    asm volatile("ldmatrix.sync.aligned.m8n8.x4.trans.shared.b16 {%0,%1,%2,%3}, [%4];" \
        : "=r"((r)[0]), "=r"((r)[1]), "=r"((r)[2]), "=r"((r)[3]) : "r"(addr))

__device__ __forceinline__ uint32_t pack2(float a, float b) {
    const __half2 h = __floats2half2_rn(a, b);
    return *(const uint32_t*)&h;
}

// ===========================================================================
// Merged prep: f32->f16 of x, w_qkv, w_out + rope tables. One launch.
// ===========================================================================
#define N4_X  8388608
#define N4_WQ 3145728
#define N4_WO 1048576
#define N4_TOTAL (N4_X + N4_WQ + N4_WO)

__global__ void prep_all(const float* __restrict__ x,
                         const float* __restrict__ wq,
                         const float* __restrict__ wo)
{
    const int i = blockIdx.x * blockDim.x + threadIdx.x;
    if (i < 512 * 32) {
        const int t = i >> 5, j = i & 31;
        const double freq = pow(10000.0, -(double)j / 32.0);
        const double ang = (double)t * freq;
        g_cos[i] = (float)cos(ang);
        g_sin[i] = (float)sin(ang);
    }
    if (i >= N4_TOTAL) return;
    const float* in;
    __half* out;
    int idx = i;
    if (idx < N4_X) { in = x; out = g_xh; }
    else if (idx < N4_X + N4_WQ) { idx -= N4_X; in = wq; out = g_wqh; }
    else { idx -= N4_X + N4_WQ; in = wo; out = g_woh; }
    const float4 v = ((const float4*)in)[idx];
    ((__half2*)out)[idx * 2]     = __floats2half2_rn(v.x, v.y);
    ((__half2*)out)[idx * 2 + 1] = __floats2half2_rn(v.z, v.w);
}

// ===========================================================================
// fp16 mma.sync GEMM: 128x128 CTA tile, BK=64, 4 warps (2x2) x 64x64 warp
// tile, 128 threads, 2-stage cp.async, 2 CTA/SM.
// MODE 0: fp32 row-major store.
// MODE 1: scatter q/k/v fp16 [B,H,T,D] with FUSED ROPE (+1/sqrt(D) q-scale):
//   thread holds rope pair (j, j+32) at (nf, nf+4) when wn==0 -> local rotate.
// ===========================================================================
#define GEMM_SMEM_BYTES 65536

template <int MODE>
__global__ void __launch_bounds__(128, 2) gemm_h(
    const __half* __restrict__ A, const __half* __restrict__ Bm,
    float* __restrict__ Cout, int M, int N, int K)
{
    extern __shared__ char smraw[];
    const uint32_t sb = smem_u32(smraw);
    const int tid = threadIdx.x;
    const int warp = tid >> 5, lane = tid & 31;
    const int wm = warp >> 1, wn = warp & 1;
    const int m0 = blockIdx.y * 128, n0 = blockIdx.x * 128;
    const int lrow = lane & 15, lcol = (lane >> 4) * 16;

    float acc[4][8][4];
#pragma unroll
    for (int i = 0; i < 4; i++)
#pragma unroll
        for (int j = 0; j < 8; j++)
#pragma unroll
            for (int q = 0; q < 4; q++) acc[i][j][q] = 0.f;

    const int nch = K / 64;

    auto load_chunk = [&](int c, int buf) {
        const int k0 = c * 64;
        const uint32_t abase = sb + buf * 32768;
        const uint32_t bbase = abase + 16384;
#pragma unroll
        for (int it = 0; it < 8; it++) {
            const int t = tid + it * 128;
            const int row = t >> 3, ch = t & 7;
            CP_ASYNC16(abase + swz((uint32_t)(row * 128 + ch * 16)),
                       A + (size_t)(m0 + row) * K + k0 + ch * 8);
        }
#pragma unroll
        for (int it = 0; it < 8; it++) {
            const int t = tid + it * 128;
            const int row = t >> 3, ch = t & 7;
            CP_ASYNC16(bbase + swz((uint32_t)(row * 128 + ch * 16)),
                       Bm + (size_t)(n0 + row) * K + k0 + ch * 8);
        }
    };

    load_chunk(0, 0);
    CP_COMMIT();

    for (int c = 0; c < nch; c++) {
        const int buf = c & 1;
        const bool has_next = (c + 1 < nch);
        if (has_next) {
            load_chunk(c + 1, (c + 1) & 1);
            CP_COMMIT();
            CP_WAIT1();
        } else {
            CP_WAIT0();
        }
        __syncthreads();

        const uint32_t abase = sb + buf * 32768;
        const uint32_t bbase = abase + 16384;

#pragma unroll
        for (int ks = 0; ks < 4; ks++) {
            uint32_t a[4][4], b[4][4];
#pragma unroll
            for (int mf = 0; mf < 4; mf++) {
                const int row = wm * 64 + mf * 16 + lrow;
                LDMX4(a[mf], abase + swz((uint32_t)(row * 128 + ks * 32 + lcol)));
            }
#pragma unroll
            for (int nb = 0; nb < 4; nb++) {
                const int row = wn * 64 + nb * 16 + lrow;
                LDMX4(b[nb], bbase + swz((uint32_t)(row * 128 + ks * 32 + lcol)));
            }
#pragma unroll
            for (int mf = 0; mf < 4; mf++)
#pragma unroll
                for (int nf = 0; nf < 8; nf++) {
                    const int nb = nf >> 1, i = nf & 1;
                    MMA_F16(acc[mf][nf], a[mf][0], a[mf][1], a[mf][2], a[mf][3],
                            b[nb][i], b[nb][i + 2]);
                }
        }
        __syncthreads();
    }

    const int g = lane >> 2, tig = lane & 3;
    if (MODE == 0) {
#pragma unroll
        for (int mf = 0; mf < 4; mf++) {
            const int mA = m0 + wm * 64 + mf * 16 + g;
#pragma unroll
            for (int nf = 0; nf < 8; nf++) {
                const int nn = n0 + wn * 64 + nf * 8 + tig * 2;
                *(float2*)(Cout + (size_t)mA * N + nn) =
                    make_float2(acc[mf][nf][0], acc[mf][nf][1]);
                *(float2*)(Cout + (size_t)(mA + 8) * N + nn) =
                    make_float2(acc[mf][nf][2], acc[mf][nf][3]);
            }
        }
    } else {
        const int which = n0 >> 11;      // 0=q, 1=k, 2=v (uniform per CTA)
        const int h = (n0 & 2047) >> 7;
        __half* basep = (which == 0) ? g_qh : (which == 1) ? g_kh : g_vh;
        const float scale = (which == 0) ? 0.08838834764831845f : 1.0f;

        if (which <= 1 && wn == 0) {
            // rope dims d = 0..63: rotate pairs (nf, nf+4) = (j, j+32), then scale
#pragma unroll
            for (int mf = 0; mf < 4; mf++) {
                const int mA = m0 + wm * 64 + mf * 16 + g;
                const int bA = mA >> 9, tA = mA & 511;
                const int mB = mA + 8;
                const int bB = mB >> 9, tB = mB & 511;
#pragma unroll
                for (int nf = 0; nf < 4; nf++) {
                    const int j0 = nf * 8 + tig * 2;   // 0..30
                    const float cA0 = g_cos[tA * 32 + j0], sA0 = g_sin[tA * 32 + j0];
                    const float cA1 = g_cos[tA * 32 + j0 + 1], sA1 = g_sin[tA * 32 + j0 + 1];
                    const float cB0 = g_cos[tB * 32 + j0], sB0 = g_sin[tB * 32 + j0];
                    const float cB1 = g_cos[tB * 32 + j0 + 1], sB1 = g_sin[tB * 32 + j0 + 1];
                    const float x1A0 = acc[mf][nf][0], x2A0 = acc[mf][nf + 4][0];
                    const float x1A1 = acc[mf][nf][1], x2A1 = acc[mf][nf + 4][1];
                    const float x1B0 = acc[mf][nf][2], x2B0 = acc[mf][nf + 4][2];
                    const float x1B1 = acc[mf][nf][3], x2B1 = acc[mf][nf + 4][3];
                    const size_t iA = ((size_t)(bA * 16 + h) * 512 + tA) * 128 + j0;
                    const size_t iB = ((size_t)(bB * 16 + h) * 512 + tB) * 128 + j0;
                    *(__half2*)&basep[iA] = __floats2half2_rn(
                        (x1A0 * cA0 - x2A0 * sA0) * scale, (x1A1 * cA1 - x2A1 * sA1) * scale);
                    *(__half2*)&basep[iA + 32] = __floats2half2_rn(
                        (x2A0 * cA0 + x1A0 * sA0) * scale, (x2A1 * cA1 + x1A1 * sA1) * scale);
                    *(__half2*)&basep[iB] = __floats2half2_rn(
                        (x1B0 * cB0 - x2B0 * sB0) * scale, (x1B1 * cB1 - x2B1 * sB1) * scale);
                    *(__half2*)&basep[iB + 32] = __floats2half2_rn(
                        (x2B0 * cB0 + x1B0 * sB0) * scale, (x2B1 * cB1 + x1B1 * sB1) * scale);
                }
            }
        } else {
            // pass-through dims (q: scaled; k d>=64 and all v: plain)
#pragma unroll
            for (int mf = 0; mf < 4; mf++) {
                const int mA = m0 + wm * 64 + mf * 16 + g;
                const int bA = mA >> 9, tA = mA & 511;
                const int mB = mA + 8;
                const int bB = mB >> 9, tB = mB & 511;
#pragma unroll
                for (int nf = 0; nf < 8; nf++) {
                    const int d = wn * 64 + nf * 8 + tig * 2;
                    const size_t iA = ((size_t)(bA * 16 + h) * 512 + tA) * 128 + d;
                    const size_t iB = ((size_t)(bB * 16 + h) * 512 + tB) * 128 + d;
                    *(__half2*)&basep[iA] = __floats2half2_rn(
                        acc[mf][nf][0] * scale, acc[mf][nf][1] * scale);
                    *(__half2*)&basep[iB] = __floats2half2_rn(
                        acc[mf][nf][2] * scale, acc[mf][nf][3] * scale);
                }
            }
        }
    }
}

// ===========================================================================
// Register-resident fp16 flash attention (R14, best known).
// Tq=64, 4 warps (16 q-rows each), full 64 keys x 128 d per warp.
// P in registers; warp-local softmax. Double-buffered K/V. 2 CTA/SM.
// ===========================================================================
#define ASQ   0                        // 64 x 272B
#define ASK(b) (17408 + (b) * 17408)   // 2 x 64x272B
#define ASV(b) (52224 + (b) * 17408)   // 2 x 64x272B
#define ATTN2_SMEM_BYTES 87040

__global__ void __launch_bounds__(128, 2) attn_mma()
{
    extern __shared__ char smc[];
    const uint32_t sb = smem_u32(smc);
    const int tid = threadIdx.x;
    const int warp = tid >> 5, lane = tid & 31;
    const int g = lane >> 2, tig = lane & 3;
    const int lrow = lane & 15, lcol = (lane >> 4) * 16;
    const int qt = blockIdx.x, hh = blockIdx.y, bb = blockIdx.z;
    const int bh = bb * 16 + hh, q0 = qt * 64;
    const int arow = warp * 16;

    const __half* qbase = g_qh + (size_t)bh * 512 * 128;
    const __half* kbase = g_kh + (size_t)bh * 512 * 128;
    const __half* vbase = g_vh + (size_t)bh * 512 * 128;

    auto stage = [&](uint32_t dstB, const __half* src) {
#pragma unroll
        for (int it = 0; it < 8; it++) {
            const int p = tid + it * 128;
            const int row = p >> 4, ch = p & 15;
            CP_ASYNC16(sb + dstB + row * 272 + ch * 16,
                       src + row * 128 + ch * 8);
        }
    };

    const int nkt = qt + 1;
    stage(ASQ, qbase + (size_t)q0 * 128);
    stage(ASK(0), kbase);
    stage(ASV(0), vbase);
    CP_COMMIT();
    if (nkt > 1) {
        stage(ASK(1), kbase + 64 * 128);
        stage(ASV(1), vbase + 64 * 128);
        CP_COMMIT();
    }

    float o[16][4];
#pragma unroll
    for (int i = 0; i < 16; i++)
#pragma unroll
        for (int q = 0; q < 4; q++) o[i][q] = 0.f;
    float mA = -1e30f, mB = -1e30f, lA = 0.f, lB = 0.f;

    for (int kt = 0; kt < nkt; kt++) {
        const int buf = kt & 1;
        if (kt < nkt - 1) { CP_WAIT1(); } else { CP_WAIT0(); }
        __syncthreads();

        float sacc[8][4];
#pragma unroll
        for (int nf = 0; nf < 8; nf++)
#pragma unroll
            for (int q = 0; q < 4; q++) sacc[nf][q] = 0.f;

#pragma unroll
        for (int dc = 0; dc < 8; dc++) {
            uint32_t a[4];
            LDMX4(a, sb + ASQ + (uint32_t)((arow + lrow) * 272 + dc * 32 + lcol));
#pragma unroll
            for (int nb = 0; nb < 4; nb++) {
                uint32_t bf[4];
                LDMX4(bf, sb + ASK(buf) +
                      (uint32_t)((nb * 16 + lrow) * 272 + dc * 32 + lcol));
#pragma unroll
                for (int i = 0; i < 2; i++)
                    MMA_F16(sacc[nb * 2 + i], a[0], a[1], a[2], a[3],
                            bf[i], bf[i + 2]);
            }
        }

        if (kt == qt) {
            const int lrA = arow + g, lrB = lrA + 8;
#pragma unroll
            for (int nf = 0; nf < 8; nf++) {
                const int lc = nf * 8 + 2 * tig;
                if (lc > lrA)     sacc[nf][0] = -1e30f;
                if (lc + 1 > lrA) sacc[nf][1] = -1e30f;
                if (lc > lrB)     sacc[nf][2] = -1e30f;
                if (lc + 1 > lrB) sacc[nf][3] = -1e30f;
            }
        }

        float mAn = -1e30f, mBn = -1e30f;
#pragma unroll
        for (int nf = 0; nf < 8; nf++) {
            mAn = fmaxf(mAn, fmaxf(sacc[nf][0], sacc[nf][1]));
            mBn = fmaxf(mBn, fmaxf(sacc[nf][2], sacc[nf][3]));
        }
        mAn = fmaxf(mAn, __shfl_xor_sync(0xffffffffu, mAn, 1));
        mAn = fmaxf(mAn, __shfl_xor_sync(0xffffffffu, mAn, 2));
        mBn = fmaxf(mBn, __shfl_xor_sync(0xffffffffu, mBn, 1));
        mBn = fmaxf(mBn, __shfl_xor_sync(0xffffffffu, mBn, 2));
        const float mAnew = fmaxf(mA, mAn), mBnew = fmaxf(mB, mBn);
        const float alA = __expf(mA - mAnew), alB = __expf(mB - mBnew);
        mA = mAnew; mB = mBnew;

        uint32_t pf[4][4];
        float sA = 0.f, sB = 0.f;
#pragma unroll
        for (int kc = 0; kc < 4; kc++) {
            const float p0 = __expf(sacc[2 * kc][0] - mA);
            const float p1 = __expf(sacc[2 * kc][1] - mA);
            const float p2 = __expf(sacc[2 * kc][2] - mB);
            const float p3 = __expf(sacc[2 * kc][3] - mB);
            const float p4 = __expf(sacc[2 * kc + 1][0] - mA);
            const float p5 = __expf(sacc[2 * kc + 1][1] - mA);
            const float p6 = __expf(sacc[2 * kc + 1][2] - mB);
            const float p7 = __expf(sacc[2 * kc + 1][3] - mB);
            sA += p0 + p1 + p4 + p5;
            sB += p2 + p3 + p6 + p7;
            pf[kc][0] = pack2(p0, p1);
            pf[kc][1] = pack2(p2, p3);
            pf[kc][2] = pack2(p4, p5);
            pf[kc][3] = pack2(p6, p7);
        }
        sA += __shfl_xor_sync(0xffffffffu, sA, 1);
        sA += __shfl_xor_sync(0xffffffffu, sA, 2);
        sB += __shfl_xor_sync(0xffffffffu, sB, 1);
        sB += __shfl_xor_sync(0xffffffffu, sB, 2);
        lA = lA * alA + sA;
        lB = lB * alB + sB;

#pragma unroll
        for (int i = 0; i < 16; i++) {
            o[i][0] *= alA; o[i][1] *= alA;
            o[i][2] *= alB; o[i][3] *= alB;
        }

#pragma unroll
        for (int kc = 0; kc < 4; kc++) {
#pragma unroll
            for (int dblk = 0; dblk < 8; dblk++) {
                uint32_t bf[4];
                LDMX4T(bf, sb + ASV(buf) +
                       (uint32_t)((kc * 16 + lrow) * 272 + dblk * 32 + lcol));
                MMA_F16(o[dblk * 2],     pf[kc][0], pf[kc][1], pf[kc][2], pf[kc][3],
                        bf[0], bf[1]);
                MMA_F16(o[dblk * 2 + 1], pf[kc][0], pf[kc][1], pf[kc][2], pf[kc][3],
                        bf[2], bf[3]);
            }
        }
        __syncthreads();

        if (kt + 2 < nkt) {
            const int knext = (kt + 2) * 64;
            stage(ASK(buf), kbase + (size_t)knext * 128);
            stage(ASV(buf), vbase + (size_t)knext * 128);
            CP_COMMIT();
        }
    }

    const float invA = 1.f / lA, invB = 1.f / lB;
    const int tA = q0 + arow + g, tB = tA + 8;
#pragma unroll
    for (int nf2 = 0; nf2 < 16; nf2++) {
        const int d = nf2 * 8 + 2 * tig;
        *(__half2*)&g_yh[((size_t)bb * 512 + tA) * 2048 + hh * 128 + d] =
            __floats2half2_rn(o[nf2][0] * invA, o[nf2][1] * invA);
        *(__half2*)&g_yh[((size_t)bb * 512 + tB) * 2048 + hh * 128 + d] =
            __floats2half2_rn(o[nf2][2] * invB, o[nf2][3] * invB);
    }
}

// ---------------------------------------------------------------------------
extern "C" void kernel_launch(void* const* d_in, const int* in_sizes, int n_in,
                              void* d_out, int out_size)
{
    (void)in_sizes; (void)n_in; (void)out_size;
    const float* x     = (const float*)d_in[0];
    const float* w_qkv = (const float*)d_in[1];
    const float* w_out = (const float*)d_in[2];
    float* out = (float*)d_out;

    __half *xh_ptr, *wqh_ptr, *woh_ptr, *yh_ptr;
    cudaGetSymbolAddress((void**)&xh_ptr,  g_xh);
    cudaGetSymbolAddress((void**)&wqh_ptr, g_wqh);
    cudaGetSymbolAddress((void**)&woh_ptr, g_woh);
    cudaGetSymbolAddress((void**)&yh_ptr,  g_yh);

    cudaFuncSetAttribute(gemm_h<1>, cudaFuncAttributeMaxDynamicSharedMemorySize, GEMM_SMEM_BYTES);
    cudaFuncSetAttribute(gemm_h<0>, cudaFuncAttributeMaxDynamicSharedMemorySize, GEMM_SMEM_BYTES);
    cudaFuncSetAttribute(attn_mma, cudaFuncAttributeMaxDynamicSharedMemorySize, ATTN2_SMEM_BYTES);

    // 0) merged prep (fp16 converts + rope tables; tables needed by gemm1 epilogue)
    prep_all<<<(N4_TOTAL + 255) / 256, 256>>>(x, w_qkv, w_out);

    // 1) QKV projection with fused rope (+q scale) in epilogue
    {
        dim3 grid(6144 / 128, 16384 / 128);
        gemm_h<1><<<grid, 128, GEMM_SMEM_BYTES>>>(xh_ptr, wqh_ptr, nullptr, 16384, 6144, 2048);
    }
    // 2) Attention (register-resident flash, Tq=64, 2 CTA/SM)
    {
        dim3 grid(8, 16, 32);
        attn_mma<<<grid, 128, ATTN2_SMEM_BYTES>>>();
    }
    // 3) Output projection
    {
        dim3 grid(2048 / 128, 16384 / 128);
        gemm_h<0><<<grid, 128, GEMM_SMEM_BYTES>>>(yh_ptr, woh_ptr, out, 16384, 2048, 2048);
    }
}